// round 9
// baseline (speedup 1.0000x reference)
#include <cuda_runtime.h>
#include <cuda_bf16.h>
#include <cstdint>
#include <math.h>

// ---------------- static scratch (no allocations allowed) ----------------
#define NB 2
#define CQ 64
#define HWA 4096         // 64*64 spatial positions

__device__ float g_fa[NB*CQ*HWA];        // fp32 features, pre-norm
__device__ float g_fb[NB*CQ*HWA];
__device__ float g_meanA[NB*CQ];
__device__ float g_meanB[NB*CQ];
__device__ __nv_bfloat16 g_faH[NB*HWA*CQ];  // transposed [q][c] bf16 hi/lo
__device__ __nv_bfloat16 g_faL[NB*HWA*CQ];
__device__ __nv_bfloat16 g_fbH[NB*HWA*CQ];
__device__ __nv_bfloat16 g_fbL[NB*HWA*CQ];
__device__ float g_fc1[NB*3*128*128];
__device__ float g_fc2[NB*3*64*64];
__device__ float g_warp[NB*3*4096];
__device__ float g_c1[NB*3*128*128];
__device__ float g_tmax[NB*32*HWA];      // per (n, p-tile, q) partial softmax stats
__device__ float g_tsum[NB*32*HWA];
__device__ float g_M[NB*HWA];            // final per-(n,q) max
__device__ float g_Li[NB*HWA];           // final per-(n,q) 1/sumexp

__device__ __forceinline__ uint32_t smem_u32(const void* p) {
    uint32_t a;
    asm("{ .reg .u64 t; cvta.to.shared.u64 t, %1; cvt.u32.u64 %0, t; }" : "=r"(a) : "l"(p));
    return a;
}

// ---------------- 1x1 conv as GEMM, fa and fb in one launch (z selects) ----------------
__global__ void k_gemm1x1_ab(const float* __restrict__ xa, const float* __restrict__ xb,
                             const float* __restrict__ Wa, const float* __restrict__ Wb,
                             const float* __restrict__ ba, const float* __restrict__ bb,
                             float* __restrict__ oa, float* __restrict__ ob) {
    const float* x = blockIdx.z ? xb : xa;
    const float* W = blockIdx.z ? Wb : Wa;
    const float* b = blockIdx.z ? bb : ba;
    float* out = blockIdx.z ? ob : oa;

    __shared__ float sW[64][65];
    int pl  = threadIdx.x & 63;
    int cog = threadIdx.x >> 6;
    int p   = blockIdx.x * 64 + pl;
    int n   = blockIdx.y;
    const float* xn = x + (size_t)n * 256 * HWA;
    float acc[16];
#pragma unroll
    for (int k = 0; k < 16; k++) acc[k] = 0.f;

    for (int ci0 = 0; ci0 < 256; ci0 += 64) {
        __syncthreads();
        for (int i = threadIdx.x; i < 64 * 64; i += 256) {
            int co = i >> 6, cl = i & 63;
            sW[co][cl] = W[co * 256 + ci0 + cl];
        }
        __syncthreads();
#pragma unroll 4
        for (int cl = 0; cl < 64; cl++) {
            float xv = xn[(size_t)(ci0 + cl) * HWA + p];
#pragma unroll
            for (int k = 0; k < 16; k++) acc[k] += sW[cog * 16 + k][cl] * xv;
        }
    }
    float* on = out + (size_t)n * CQ * HWA;
#pragma unroll
    for (int k = 0; k < 16; k++) {
        int co = cog * 16 + k;
        on[(size_t)co * HWA + p] = acc[k] + b[co];
    }
}

// ---------------- instance norm + leaky relu, in place; optional post-act mean ----------------
// 1024 threads per block, one block per plane.
__global__ void k_in_leaky(float* __restrict__ buf, int HW, float* __restrict__ mean_out) {
    float* p = buf + (size_t)blockIdx.x * HW;
    int t = threadIdx.x;
    int nt = blockDim.x;
    __shared__ float red[1024];
    __shared__ float s_mean, s_rstd;

    float s = 0.f;
    for (int i = t; i < HW; i += nt) s += p[i];
    red[t] = s; __syncthreads();
    for (int o = nt >> 1; o > 0; o >>= 1) { if (t < o) red[t] += red[t + o]; __syncthreads(); }
    if (t == 0) s_mean = red[0] / (float)HW;
    __syncthreads();
    float mean = s_mean;

    float s2 = 0.f;
    for (int i = t; i < HW; i += nt) { float d = p[i] - mean; s2 += d * d; }
    red[t] = s2; __syncthreads();
    for (int o = nt >> 1; o > 0; o >>= 1) { if (t < o) red[t] += red[t + o]; __syncthreads(); }
    if (t == 0) s_rstd = rsqrtf(red[0] / (float)HW + 1e-5f);
    __syncthreads();
    float r = s_rstd;

    float sact = 0.f;
    for (int i = t; i < HW; i += nt) {
        float v = (p[i] - mean) * r;
        v = v >= 0.f ? v : 0.2f * v;
        p[i] = v;
        sact += v;
    }
    if (mean_out) {
        __syncthreads();
        red[t] = sact; __syncthreads();
        for (int o = nt >> 1; o > 0; o >>= 1) { if (t < o) red[t] += red[t + o]; __syncthreads(); }
        if (t == 0) mean_out[blockIdx.x] = red[0] / (float)HW;
    }
}

// fa+fb in one launch: grid (NB*CQ, 2)
__global__ void k_in_leaky_ab(float* __restrict__ fa, float* __restrict__ fb,
                              float* __restrict__ mA, float* __restrict__ mB) {
    float* buf = blockIdx.y ? fb : fa;
    float* mo  = blockIdx.y ? mB : mA;
    float* p = buf + (size_t)blockIdx.x * HWA;
    int t = threadIdx.x;
    int nt = blockDim.x;
    __shared__ float red[1024];
    __shared__ float s_mean, s_rstd;

    float s = 0.f;
    for (int i = t; i < HWA; i += nt) s += p[i];
    red[t] = s; __syncthreads();
    for (int o = nt >> 1; o > 0; o >>= 1) { if (t < o) red[t] += red[t + o]; __syncthreads(); }
    if (t == 0) s_mean = red[0] / (float)HWA;
    __syncthreads();
    float mean = s_mean;

    float s2 = 0.f;
    for (int i = t; i < HWA; i += nt) { float d = p[i] - mean; s2 += d * d; }
    red[t] = s2; __syncthreads();
    for (int o = nt >> 1; o > 0; o >>= 1) { if (t < o) red[t] += red[t + o]; __syncthreads(); }
    if (t == 0) s_rstd = rsqrtf(red[0] / (float)HWA + 1e-5f);
    __syncthreads();
    float r = s_rstd;

    float sact = 0.f;
    for (int i = t; i < HWA; i += nt) {
        float v = (p[i] - mean) * r;
        v = v >= 0.f ? v : 0.2f * v;
        p[i] = v;
        sact += v;
    }
    __syncthreads();
    red[t] = sact; __syncthreads();
    for (int o = nt >> 1; o > 0; o >>= 1) { if (t < o) red[t] += red[t + o]; __syncthreads(); }
    if (t == 0) mo[blockIdx.x] = red[0] / (float)HWA;
}

// ---------------- center + column L2 normalize, emit transposed bf16 hi/lo ----------------
// grid (16, NB, 2): z selects fa/fb
__global__ void k_colnorm_bf16(const float* __restrict__ fa, const float* __restrict__ fb,
                               const float* __restrict__ mA, const float* __restrict__ mB,
                               __nv_bfloat16* __restrict__ aH, __nv_bfloat16* __restrict__ aL,
                               __nv_bfloat16* __restrict__ bH, __nv_bfloat16* __restrict__ bL) {
    const float* buf = blockIdx.z ? fb : fa;
    const float* mean = blockIdx.z ? mB : mA;
    __nv_bfloat16* oH = blockIdx.z ? bH : aH;
    __nv_bfloat16* oL = blockIdx.z ? bL : aL;

    int n = blockIdx.y;
    int q = blockIdx.x * 256 + threadIdx.x;
    __shared__ float sm[64];
    if (threadIdx.x < 64) sm[threadIdx.x] = mean[n * 64 + threadIdx.x];
    __syncthreads();
    const float* bn = buf + (size_t)n * CQ * HWA;
    float v[64];
    float s = 0.f;
#pragma unroll
    for (int c = 0; c < 64; c++) {
        float t2 = bn[(size_t)c * HWA + q] - sm[c];
        v[c] = t2; s += t2 * t2;
    }
    float inv = 1.f / (sqrtf(s) + 1e-5f);
    __align__(16) __nv_bfloat16 hb[64];
    __align__(16) __nv_bfloat16 lb[64];
#pragma unroll
    for (int c = 0; c < 64; c++) {
        float f = v[c] * inv;
        __nv_bfloat16 h = __float2bfloat16(f);
        hb[c] = h;
        lb[c] = __float2bfloat16(f - __bfloat162float(h));
    }
    uint4* dH = (uint4*)(oH + ((size_t)n * HWA + q) * 64);
    uint4* dL = (uint4*)(oL + ((size_t)n * HWA + q) * 64);
#pragma unroll
    for (int i = 0; i < 8; i++) {
        dH[i] = ((const uint4*)hb)[i];
        dL[i] = ((const uint4*)lb)[i];
    }
}

// ---------------- energy GEMM via mma.sync bf16 hi/lo split + softmax stats epilogue ----------
#define EGY_DSMEM (4 * 16384)

__device__ __forceinline__ void ldsm_x4(uint32_t& r0, uint32_t& r1, uint32_t& r2, uint32_t& r3,
                                        uint32_t addr) {
    asm volatile("ldmatrix.sync.aligned.m8n8.x4.shared.b16 {%0,%1,%2,%3}, [%4];"
                 : "=r"(r0), "=r"(r1), "=r"(r2), "=r"(r3) : "r"(addr));
}
__device__ __forceinline__ void mma16816(float& d0, float& d1, float& d2, float& d3,
                                         uint32_t a0, uint32_t a1, uint32_t a2, uint32_t a3,
                                         uint32_t b0, uint32_t b1) {
    asm volatile(
        "mma.sync.aligned.m16n8k16.row.col.f32.bf16.bf16.f32 "
        "{%0,%1,%2,%3}, {%4,%5,%6,%7}, {%8,%9}, {%0,%1,%2,%3};"
        : "+f"(d0), "+f"(d1), "+f"(d2), "+f"(d3)
        : "r"(a0), "r"(a1), "r"(a2), "r"(a3), "r"(b0), "r"(b1));
}

__global__ void __launch_bounds__(256, 2)
k_energy_mma(const __nv_bfloat16* __restrict__ AH, const __nv_bfloat16* __restrict__ AL,
             const __nv_bfloat16* __restrict__ BH, const __nv_bfloat16* __restrict__ BL,
             float* __restrict__ E, float* __restrict__ tmax, float* __restrict__ tsum) {
    extern __shared__ __align__(16) char smem[];
    __shared__ float sstat[2][4][32][2];   // [wm][wn][col][{m,s}]
    const int tid = threadIdx.x;
    const int wid = tid >> 5, lane = tid & 31;
    const int wm = wid & 1, wn = wid >> 1;        // warp tile: rows wm*64, cols wn*32
    const int n = blockIdx.z;
    const int q0 = blockIdx.x * 128, p0 = blockIdx.y * 128;

    const int T_AH = 0, T_AL = 16384, T_BH = 32768, T_BL = 49152;

    {
        const uint4* src[4] = {
            (const uint4*)(AH + ((size_t)n * HWA + p0) * 64),
            (const uint4*)(AL + ((size_t)n * HWA + p0) * 64),
            (const uint4*)(BH + ((size_t)n * HWA + q0) * 64),
            (const uint4*)(BL + ((size_t)n * HWA + q0) * 64)};
        uint4* dst[4] = {(uint4*)(smem + T_AH), (uint4*)(smem + T_AL),
                         (uint4*)(smem + T_BH), (uint4*)(smem + T_BL)};
#pragma unroll
        for (int t4 = 0; t4 < 4; t4++) {
#pragma unroll
            for (int i = 0; i < 4; i++) {
                int g = tid + i * 256;
                int row = g >> 3, ch = g & 7;
                dst[t4][row * 8 + (ch ^ (row & 7))] = src[t4][g];
            }
        }
    }
    __syncthreads();

    const uint32_t sbase = smem_u32(smem);
    float acc[4][4][4];
#pragma unroll
    for (int a = 0; a < 4; a++)
#pragma unroll
        for (int b = 0; b < 4; b++)
#pragma unroll
            for (int r = 0; r < 4; r++) acc[a][b][r] = 0.f;

    const int aoff[3] = {T_AH, T_AH, T_AL};
    const int boff[3] = {T_BH, T_BL, T_BH};

#pragma unroll
    for (int pass = 0; pass < 3; pass++) {
        uint32_t abase = sbase + aoff[pass];
        uint32_t bbase = sbase + boff[pass];
#pragma unroll
        for (int k0 = 0; k0 < 64; k0 += 16) {
            int cbase = k0 >> 3;
            uint32_t a[4][4];
#pragma unroll
            for (int mi = 0; mi < 4; mi++) {
                int row = wm * 64 + mi * 16 + (lane & 15);
                int ch = cbase + (lane >> 4);
                uint32_t addr = abase + row * 128 + ((ch ^ (row & 7)) << 4);
                ldsm_x4(a[mi][0], a[mi][1], a[mi][2], a[mi][3], addr);
            }
            uint32_t b[4][2];
#pragma unroll
            for (int np = 0; np < 2; np++) {
                int row = wn * 32 + np * 16 + (lane & 7) + ((lane >> 4) << 3);
                int ch = cbase + ((lane >> 3) & 1);
                uint32_t addr = bbase + row * 128 + ((ch ^ (row & 7)) << 4);
                uint32_t r0, r1, r2, r3;
                ldsm_x4(r0, r1, r2, r3, addr);
                b[np * 2 + 0][0] = r0; b[np * 2 + 0][1] = r1;
                b[np * 2 + 1][0] = r2; b[np * 2 + 1][1] = r3;
            }
#pragma unroll
            for (int mi = 0; mi < 4; mi++)
#pragma unroll
                for (int ni = 0; ni < 4; ni++)
                    mma16816(acc[mi][ni][0], acc[mi][ni][1], acc[mi][ni][2], acc[mi][ni][3],
                             a[mi][0], a[mi][1], a[mi][2], a[mi][3],
                             b[ni][0], b[ni][1]);
        }
    }

    // scale by 100 in place
#pragma unroll
    for (int mi = 0; mi < 4; mi++)
#pragma unroll
        for (int ni = 0; ni < 4; ni++)
#pragma unroll
            for (int r = 0; r < 4; r++) acc[mi][ni][r] *= 100.f;

    // store E
    float* En = E + (size_t)n * HWA * HWA;
    int rbase = p0 + wm * 64 + (lane >> 2);
    int cbase2 = q0 + wn * 32 + (lane & 3) * 2;
#pragma unroll
    for (int mi = 0; mi < 4; mi++) {
#pragma unroll
        for (int ni = 0; ni < 4; ni++) {
            float2 v0 = make_float2(acc[mi][ni][0], acc[mi][ni][1]);
            float2 v1 = make_float2(acc[mi][ni][2], acc[mi][ni][3]);
            size_t r0 = (size_t)(rbase + mi * 16) * HWA + cbase2 + ni * 8;
            size_t r1 = r0 + 8 * HWA;
            *(float2*)(En + r0) = v0;
            *(float2*)(En + r1) = v1;
        }
    }

    // softmax stats over the 128 p-rows of this tile, per column.
    // thread column j (0..7): ni = j>>1, half = j&1 -> regs half, half+2; 8 p-values (4 mi x 2 rows)
    float cm[8], cs[8];
#pragma unroll
    for (int j = 0; j < 8; j++) {
        int ni = j >> 1, half = j & 1;
        float m = acc[0][ni][half];
#pragma unroll
        for (int mi = 0; mi < 4; mi++) {
            m = fmaxf(m, acc[mi][ni][half]);
            m = fmaxf(m, acc[mi][ni][half + 2]);
        }
        float s = 0.f;
#pragma unroll
        for (int mi = 0; mi < 4; mi++) {
            s += __expf(acc[mi][ni][half] - m);
            s += __expf(acc[mi][ni][half + 2] - m);
        }
        cm[j] = m; cs[j] = s;
    }
    // warp reduce across lanes sharing column (xor 4, 8, 16)
#pragma unroll
    for (int off = 4; off <= 16; off <<= 1) {
#pragma unroll
        for (int j = 0; j < 8; j++) {
            float om = __shfl_xor_sync(0xFFFFFFFF, cm[j], off);
            float os = __shfl_xor_sync(0xFFFFFFFF, cs[j], off);
            float M = fmaxf(cm[j], om);
            cs[j] = cs[j] * __expf(cm[j] - M) + os * __expf(om - M);
            cm[j] = M;
        }
    }
    if ((lane >> 2) == 0) {
#pragma unroll
        for (int j = 0; j < 8; j++) {
            int cl = (j >> 1) * 8 + (lane & 3) * 2 + (j & 1);
            sstat[wm][wn][cl][0] = cm[j];
            sstat[wm][wn][cl][1] = cs[j];
        }
    }
    __syncthreads();
    if (tid < 128) {
        int wn2 = tid >> 5, cl = tid & 31;
        float m0 = sstat[0][wn2][cl][0], s0 = sstat[0][wn2][cl][1];
        float m1 = sstat[1][wn2][cl][0], s1 = sstat[1][wn2][cl][1];
        float M = fmaxf(m0, m1);
        float S = s0 * __expf(m0 - M) + s1 * __expf(m1 - M);
        size_t idx = ((size_t)(n * 32 + blockIdx.y)) * HWA + q0 + tid;
        tmax[idx] = M;
        tsum[idx] = S;
    }
}

// ---------------- combine per-tile stats -> per-(n,q) M and 1/L ----------------
__global__ void k_stats_final(const float* __restrict__ tmax, const float* __restrict__ tsum,
                              float* __restrict__ Mv, float* __restrict__ Lv) {
    int n = blockIdx.y;
    int q = blockIdx.x * 128 + threadIdx.x;
    float M = -1e30f;
#pragma unroll 4
    for (int pt = 0; pt < 32; pt++)
        M = fmaxf(M, tmax[((size_t)(n * 32 + pt)) * HWA + q]);
    float L = 0.f;
#pragma unroll 4
    for (int pt = 0; pt < 32; pt++) {
        size_t idx = ((size_t)(n * 32 + pt)) * HWA + q;
        L += tsum[idx] * __expf(tmax[idx] - M);
    }
    Mv[n * HWA + q] = M;
    Lv[n * HWA + q] = 1.f / L;
}

// ---------------- single-pass softmax write + fc_warp einsum ----------------
__global__ void k_softmax_fused(float* __restrict__ E, const float* __restrict__ Mv,
                                const float* __restrict__ Lv, const float* __restrict__ fc,
                                float* __restrict__ warp) {
    int ql = threadIdx.x & 31;
    int pg = threadIdx.x >> 5;
    int n = blockIdx.y;
    int q = blockIdx.x * 32 + ql;
    float* En = E + (size_t)n * HWA * HWA;
    float M = Mv[n * HWA + q];
    float Li = Lv[n * HWA + q];

    const float* f0 = fc + (size_t)(n * 3 + 0) * HWA;
    const float* f1 = fc + (size_t)(n * 3 + 1) * HWA;
    const float* f2 = fc + (size_t)(n * 3 + 2) * HWA;
    float w0 = 0.f, w1 = 0.f, w2 = 0.f;
#pragma unroll 4
    for (int p = pg; p < HWA; p += 8) {
        size_t off = (size_t)p * HWA + q;
        float w = __expf(En[off] - M) * Li;
        En[off] = w;
        w0 += __ldg(f0 + p) * w;
        w1 += __ldg(f1 + p) * w;
        w2 += __ldg(f2 + p) * w;
    }
    __shared__ float sw[3][8][32];
    sw[0][pg][ql] = w0; sw[1][pg][ql] = w1; sw[2][pg][ql] = w2;
    __syncthreads();
    if (pg == 0) {
        float a0 = 0.f, a1 = 0.f, a2 = 0.f;
#pragma unroll
        for (int g = 0; g < 8; g++) { a0 += sw[0][g][ql]; a1 += sw[1][g][ql]; a2 += sw[2][g][ql]; }
        warp[(size_t)(n * 3 + 0) * HWA + q] = a0;
        warp[(size_t)(n * 3 + 1) * HWA + q] = a1;
        warp[(size_t)(n * 3 + 2) * HWA + q] = a2;
    }
}

// ---------------- 3x3 conv, reflect pad 1, stride 2, 3->3 channels ----------------
__global__ void k_conv_refl_s2(const float* __restrict__ x, const float* __restrict__ W,
                               const float* __restrict__ b, float* __restrict__ y, int Hin) {
    int Hout = Hin / 2;
    int total = NB * 3 * Hout * Hout;
    int idx = blockIdx.x * 256 + threadIdx.x;
    if (idx >= total) return;
    int ow = idx % Hout; int t = idx / Hout;
    int oh = t % Hout; t /= Hout;
    int co = t % 3; int n = t / 3;
    float s = b[co];
#pragma unroll
    for (int ci = 0; ci < 3; ci++) {
        const float* xp = x + (size_t)((n * 3 + ci) * Hin) * Hin;
#pragma unroll
        for (int kh = 0; kh < 3; kh++) {
            int ih = 2 * oh + kh - 1;
            if (ih < 0) ih = -ih; else if (ih >= Hin) ih = 2 * Hin - 2 - ih;
#pragma unroll
            for (int kw = 0; kw < 3; kw++) {
                int iw = 2 * ow + kw - 1;
                if (iw < 0) iw = -iw; else if (iw >= Hin) iw = 2 * Hin - 2 - iw;
                s += W[((co * 3 + ci) * 3 + kh) * 3 + kw] * __ldg(xp + ih * Hin + iw);
            }
        }
    }
    y[idx] = s;
}

// ---------------- fused 2x bilinear upsample (align_corners) + 3x3 conv zero-pad ----------------
__global__ void k_upconv(const float* __restrict__ x, const float* __restrict__ W,
                         const float* __restrict__ b, float* __restrict__ y, int S) {
    int O = 2 * S;
    int total = NB * 3 * O * O;
    int idx = blockIdx.x * 256 + threadIdx.x;
    if (idx >= total) return;
    int ow = idx % O; int t = idx / O;
    int oh = t % O; t /= O;
    int co = t % 3; int n = t / 3;
    float s = b[co];
    float rs = (float)(S - 1) / (float)(O - 1);
#pragma unroll
    for (int kh = 0; kh < 3; kh++) {
        int r = oh + kh - 1;
        if (r < 0 || r >= O) continue;
        float ph = (float)r * rs;
        int i0 = (int)ph; float fh = ph - (float)i0; int i1 = min(i0 + 1, S - 1);
#pragma unroll
        for (int kw = 0; kw < 3; kw++) {
            int c = ow + kw - 1;
            if (c < 0 || c >= O) continue;
            float pw = (float)c * rs;
            int j0 = (int)pw; float fw = pw - (float)j0; int j1 = min(j0 + 1, S - 1);
#pragma unroll
            for (int ci = 0; ci < 3; ci++) {
                const float* xp = x + (size_t)((n * 3 + ci) * S) * S;
                float top = __ldg(xp + i0 * S + j0) * (1.f - fh) + __ldg(xp + i1 * S + j0) * fh;
                float bot = __ldg(xp + i0 * S + j1) * (1.f - fh) + __ldg(xp + i1 * S + j1) * fh;
                float v = top * (1.f - fw) + bot * fw;
                s += W[((co * 3 + ci) * 3 + kh) * 3 + kw] * v;
            }
        }
    }
    y[idx] = s;
}

// ---------------- host side ----------------
static float* symf(const void* s) {
    void* p = nullptr;
    cudaGetSymbolAddress(&p, s);
    return (float*)p;
}
static __nv_bfloat16* symb(const void* s) {
    void* p = nullptr;
    cudaGetSymbolAddress(&p, s);
    return (__nv_bfloat16*)p;
}

extern "C" void kernel_launch(void* const* d_in, const int* in_sizes, int n_in,
                              void* d_out, int out_size) {
    const float* fa_raw = (const float*)d_in[0];
    const float* fb_raw = (const float*)d_in[1];
    const float* fc_raw = (const float*)d_in[2];
    const float* Wa  = (const float*)d_in[3];
    const float* ba  = (const float*)d_in[4];
    const float* Wb  = (const float*)d_in[5];
    const float* bb  = (const float*)d_in[6];
    const float* Wc1 = (const float*)d_in[7];
    const float* bc1 = (const float*)d_in[8];
    const float* Wc2 = (const float*)d_in[9];
    const float* bc2 = (const float*)d_in[10];
    const float* Wu1 = (const float*)d_in[11];
    const float* bu1 = (const float*)d_in[12];
    const float* Wu2 = (const float*)d_in[13];
    const float* bu2 = (const float*)d_in[14];

    float* out = (float*)d_out;
    float* fcw  = out;                               // [2,3,256,256]
    float* corr = out + (size_t)NB * 3 * 256 * 256;  // [2,4096,4096]

    float* fa   = symf(g_fa);
    float* fb   = symf(g_fb);
    float* mA   = symf(g_meanA);
    float* mB   = symf(g_meanB);
    __nv_bfloat16* faH = symb(g_faH);
    __nv_bfloat16* faL = symb(g_faL);
    __nv_bfloat16* fbH = symb(g_fbH);
    __nv_bfloat16* fbL = symb(g_fbL);
    float* fc1  = symf(g_fc1);
    float* fc2  = symf(g_fc2);
    float* warp = symf(g_warp);
    float* c1   = symf(g_c1);
    float* tmax = symf(g_tmax);
    float* tsum = symf(g_tsum);
    float* Mv   = symf(g_M);
    float* Lv   = symf(g_Li);

    cudaFuncSetAttribute(k_energy_mma, cudaFuncAttributeMaxDynamicSharedMemorySize, EGY_DSMEM);

    // fa / fb feature path (merged launches)
    k_gemm1x1_ab<<<dim3(64, NB, 2), 256>>>(fa_raw, fb_raw, Wa, Wb, ba, bb, fa, fb);
    k_in_leaky_ab<<<dim3(NB * CQ, 2), 1024>>>(fa, fb, mA, mB);
    k_colnorm_bf16<<<dim3(16, NB, 2), 256>>>(fa, fb, mA, mB, faH, faL, fbH, fbL);

    // fc downsample path
    k_conv_refl_s2<<<(NB * 3 * 128 * 128 + 255) / 256, 256>>>(fc_raw, Wc1, bc1, fc1, 256);
    k_in_leaky<<<NB * 3, 1024>>>(fc1, 128 * 128, nullptr);
    k_conv_refl_s2<<<(NB * 3 * 64 * 64 + 255) / 256, 256>>>(fc1, Wc2, bc2, fc2, 128);
    k_in_leaky<<<NB * 3, 1024>>>(fc2, 64 * 64, nullptr);

    // energy GEMM + per-tile softmax stats into corr region of d_out
    k_energy_mma<<<dim3(32, 32, NB), 256, EGY_DSMEM>>>(fbH, fbL, faH, faL, corr, tmax, tsum);
    k_stats_final<<<dim3(32, NB), 128>>>(tmax, tsum, Mv, Lv);

    // single-pass softmax write (in place) + fc_warp einsum
    k_softmax_fused<<<dim3(128, NB), 256>>>(corr, Mv, Lv, fc2, warp);

    // upsample block 1: 64 -> 128 (fused up+conv)
    k_upconv<<<(NB * 3 * 128 * 128 + 255) / 256, 256>>>(warp, Wu1, bu1, c1, 64);
    k_in_leaky<<<NB * 3, 1024>>>(c1, 128 * 128, nullptr);

    // upsample block 2: 128 -> 256, final result into d_out fc_warp region
    k_upconv<<<(NB * 3 * 256 * 256 + 255) / 256, 256>>>(c1, Wu2, bu2, fcw, 128);
    k_in_leaky<<<NB * 3, 1024>>>(fcw, 256 * 256, nullptr);
}

// round 10
// speedup vs baseline: 1.9906x; 1.9906x over previous
#include <cuda_runtime.h>
#include <cuda_bf16.h>
#include <cstdint>
#include <math.h>

// ---------------- static scratch (no allocations allowed) ----------------
#define NB 2
#define CQ 64
#define HWA 4096         // 64*64 spatial positions

__device__ float g_fa[NB*CQ*HWA];        // fp32 features, pre-norm
__device__ float g_fb[NB*CQ*HWA];
__device__ float g_meanA[NB*CQ];
__device__ float g_meanB[NB*CQ];
__device__ __nv_bfloat16 g_faH[NB*HWA*CQ];  // transposed [q][c] bf16 hi/lo
__device__ __nv_bfloat16 g_faL[NB*HWA*CQ];
__device__ __nv_bfloat16 g_fbH[NB*HWA*CQ];
__device__ __nv_bfloat16 g_fbL[NB*HWA*CQ];
__device__ float g_fc1[NB*3*128*128];
__device__ float g_fc2[NB*3*64*64];
__device__ float g_warp[NB*3*4096];
__device__ float g_up1[NB*3*128*128];
__device__ float g_c1[NB*3*128*128];
__device__ float g_up2[NB*3*256*256];
__device__ float g_tmax[NB*32*HWA];      // per (n, p-tile, q) partial softmax stats
__device__ float g_tsum[NB*32*HWA];
__device__ float g_M[NB*HWA];            // final per-(n,q) max
__device__ float g_Li[NB*HWA];           // final per-(n,q) 1/sumexp

__device__ __forceinline__ uint32_t smem_u32(const void* p) {
    uint32_t a;
    asm("{ .reg .u64 t; cvta.to.shared.u64 t, %1; cvt.u32.u64 %0, t; }" : "=r"(a) : "l"(p));
    return a;
}

// ---------------- 1x1 conv as GEMM, fa and fb in one launch (z selects) ----------------
__global__ void k_gemm1x1_ab(const float* __restrict__ xa, const float* __restrict__ xb,
                             const float* __restrict__ Wa, const float* __restrict__ Wb,
                             const float* __restrict__ ba, const float* __restrict__ bb,
                             float* __restrict__ oa, float* __restrict__ ob) {
    const float* x = blockIdx.z ? xb : xa;
    const float* W = blockIdx.z ? Wb : Wa;
    const float* b = blockIdx.z ? bb : ba;
    float* out = blockIdx.z ? ob : oa;

    __shared__ float sW[64][65];
    int pl  = threadIdx.x & 63;
    int cog = threadIdx.x >> 6;
    int p   = blockIdx.x * 64 + pl;
    int n   = blockIdx.y;
    const float* xn = x + (size_t)n * 256 * HWA;
    float acc[16];
#pragma unroll
    for (int k = 0; k < 16; k++) acc[k] = 0.f;

    for (int ci0 = 0; ci0 < 256; ci0 += 64) {
        __syncthreads();
        for (int i = threadIdx.x; i < 64 * 64; i += 256) {
            int co = i >> 6, cl = i & 63;
            sW[co][cl] = W[co * 256 + ci0 + cl];
        }
        __syncthreads();
#pragma unroll 4
        for (int cl = 0; cl < 64; cl++) {
            float xv = xn[(size_t)(ci0 + cl) * HWA + p];
#pragma unroll
            for (int k = 0; k < 16; k++) acc[k] += sW[cog * 16 + k][cl] * xv;
        }
    }
    float* on = out + (size_t)n * CQ * HWA;
#pragma unroll
    for (int k = 0; k < 16; k++) {
        int co = cog * 16 + k;
        on[(size_t)co * HWA + p] = acc[k] + b[co];
    }
}

// ---------------- instance norm + leaky relu, in place ----------------
__global__ void k_in_leaky(float* __restrict__ buf, int HW) {
    float* p = buf + (size_t)blockIdx.x * HW;
    int t = threadIdx.x;
    int nt = blockDim.x;
    __shared__ float red[1024];
    __shared__ float s_mean, s_rstd;

    float s = 0.f;
    for (int i = t; i < HW; i += nt) s += p[i];
    red[t] = s; __syncthreads();
    for (int o = nt >> 1; o > 0; o >>= 1) { if (t < o) red[t] += red[t + o]; __syncthreads(); }
    if (t == 0) s_mean = red[0] / (float)HW;
    __syncthreads();
    float mean = s_mean;

    float s2 = 0.f;
    for (int i = t; i < HW; i += nt) { float d = p[i] - mean; s2 += d * d; }
    red[t] = s2; __syncthreads();
    for (int o = nt >> 1; o > 0; o >>= 1) { if (t < o) red[t] += red[t + o]; __syncthreads(); }
    if (t == 0) s_rstd = rsqrtf(red[0] / (float)HW + 1e-5f);
    __syncthreads();
    float r = s_rstd;

    for (int i = t; i < HW; i += nt) {
        float v = (p[i] - mean) * r;
        p[i] = v >= 0.f ? v : 0.2f * v;
    }
}

// fa+fb in one launch: grid (NB*CQ, 2); also emits post-activation spatial mean
__global__ void k_in_leaky_ab(float* __restrict__ fa, float* __restrict__ fb,
                              float* __restrict__ mA, float* __restrict__ mB) {
    float* buf = blockIdx.y ? fb : fa;
    float* mo  = blockIdx.y ? mB : mA;
    float* p = buf + (size_t)blockIdx.x * HWA;
    int t = threadIdx.x;
    int nt = blockDim.x;
    __shared__ float red[1024];
    __shared__ float s_mean, s_rstd;

    float s = 0.f;
    for (int i = t; i < HWA; i += nt) s += p[i];
    red[t] = s; __syncthreads();
    for (int o = nt >> 1; o > 0; o >>= 1) { if (t < o) red[t] += red[t + o]; __syncthreads(); }
    if (t == 0) s_mean = red[0] / (float)HWA;
    __syncthreads();
    float mean = s_mean;

    float s2 = 0.f;
    for (int i = t; i < HWA; i += nt) { float d = p[i] - mean; s2 += d * d; }
    red[t] = s2; __syncthreads();
    for (int o = nt >> 1; o > 0; o >>= 1) { if (t < o) red[t] += red[t + o]; __syncthreads(); }
    if (t == 0) s_rstd = rsqrtf(red[0] / (float)HWA + 1e-5f);
    __syncthreads();
    float r = s_rstd;

    float sact = 0.f;
    for (int i = t; i < HWA; i += nt) {
        float v = (p[i] - mean) * r;
        v = v >= 0.f ? v : 0.2f * v;
        p[i] = v;
        sact += v;
    }
    __syncthreads();
    red[t] = sact; __syncthreads();
    for (int o = nt >> 1; o > 0; o >>= 1) { if (t < o) red[t] += red[t + o]; __syncthreads(); }
    if (t == 0) mo[blockIdx.x] = red[0] / (float)HWA;
}

// ---------------- center + column L2 normalize, emit transposed bf16 hi/lo ----------------
__global__ void k_colnorm_bf16(const float* __restrict__ fa, const float* __restrict__ fb,
                               const float* __restrict__ mA, const float* __restrict__ mB,
                               __nv_bfloat16* __restrict__ aH, __nv_bfloat16* __restrict__ aL,
                               __nv_bfloat16* __restrict__ bH, __nv_bfloat16* __restrict__ bL) {
    const float* buf = blockIdx.z ? fb : fa;
    const float* mean = blockIdx.z ? mB : mA;
    __nv_bfloat16* oH = blockIdx.z ? bH : aH;
    __nv_bfloat16* oL = blockIdx.z ? bL : aL;

    int n = blockIdx.y;
    int q = blockIdx.x * 256 + threadIdx.x;
    __shared__ float sm[64];
    if (threadIdx.x < 64) sm[threadIdx.x] = mean[n * 64 + threadIdx.x];
    __syncthreads();
    const float* bn = buf + (size_t)n * CQ * HWA;
    float v[64];
    float s = 0.f;
#pragma unroll
    for (int c = 0; c < 64; c++) {
        float t2 = bn[(size_t)c * HWA + q] - sm[c];
        v[c] = t2; s += t2 * t2;
    }
    float inv = 1.f / (sqrtf(s) + 1e-5f);
    __align__(16) __nv_bfloat16 hb[64];
    __align__(16) __nv_bfloat16 lb[64];
#pragma unroll
    for (int c = 0; c < 64; c++) {
        float f = v[c] * inv;
        __nv_bfloat16 h = __float2bfloat16(f);
        hb[c] = h;
        lb[c] = __float2bfloat16(f - __bfloat162float(h));
    }
    uint4* dH = (uint4*)(oH + ((size_t)n * HWA + q) * 64);
    uint4* dL = (uint4*)(oL + ((size_t)n * HWA + q) * 64);
#pragma unroll
    for (int i = 0; i < 8; i++) {
        dH[i] = ((const uint4*)hb)[i];
        dL[i] = ((const uint4*)lb)[i];
    }
}

// ---------------- energy GEMM via mma.sync bf16 hi/lo split + softmax stats epilogue ----------
#define EGY_DSMEM (4 * 16384)

__device__ __forceinline__ void ldsm_x4(uint32_t& r0, uint32_t& r1, uint32_t& r2, uint32_t& r3,
                                        uint32_t addr) {
    asm volatile("ldmatrix.sync.aligned.m8n8.x4.shared.b16 {%0,%1,%2,%3}, [%4];"
                 : "=r"(r0), "=r"(r1), "=r"(r2), "=r"(r3) : "r"(addr));
}
__device__ __forceinline__ void mma16816(float& d0, float& d1, float& d2, float& d3,
                                         uint32_t a0, uint32_t a1, uint32_t a2, uint32_t a3,
                                         uint32_t b0, uint32_t b1) {
    asm volatile(
        "mma.sync.aligned.m16n8k16.row.col.f32.bf16.bf16.f32 "
        "{%0,%1,%2,%3}, {%4,%5,%6,%7}, {%8,%9}, {%0,%1,%2,%3};"
        : "+f"(d0), "+f"(d1), "+f"(d2), "+f"(d3)
        : "r"(a0), "r"(a1), "r"(a2), "r"(a3), "r"(b0), "r"(b1));
}

__global__ void __launch_bounds__(256, 2)
k_energy_mma(const __nv_bfloat16* __restrict__ AH, const __nv_bfloat16* __restrict__ AL,
             const __nv_bfloat16* __restrict__ BH, const __nv_bfloat16* __restrict__ BL,
             float* __restrict__ E, float* __restrict__ tmax, float* __restrict__ tsum) {
    extern __shared__ __align__(16) char smem[];
    __shared__ float sstat[2][4][32][2];   // [wm][wn][col][{m,s}]
    const int tid = threadIdx.x;
    const int wid = tid >> 5, lane = tid & 31;
    const int wm = wid & 1, wn = wid >> 1;
    const int n = blockIdx.z;
    const int q0 = blockIdx.x * 128, p0 = blockIdx.y * 128;

    const int T_AH = 0, T_AL = 16384, T_BH = 32768, T_BL = 49152;

    {
        const uint4* src[4] = {
            (const uint4*)(AH + ((size_t)n * HWA + p0) * 64),
            (const uint4*)(AL + ((size_t)n * HWA + p0) * 64),
            (const uint4*)(BH + ((size_t)n * HWA + q0) * 64),
            (const uint4*)(BL + ((size_t)n * HWA + q0) * 64)};
        uint4* dst[4] = {(uint4*)(smem + T_AH), (uint4*)(smem + T_AL),
                         (uint4*)(smem + T_BH), (uint4*)(smem + T_BL)};
#pragma unroll
        for (int t4 = 0; t4 < 4; t4++) {
#pragma unroll
            for (int i = 0; i < 4; i++) {
                int g = tid + i * 256;
                int row = g >> 3, ch = g & 7;
                dst[t4][row * 8 + (ch ^ (row & 7))] = src[t4][g];
            }
        }
    }
    __syncthreads();

    const uint32_t sbase = smem_u32(smem);
    float acc[4][4][4];
#pragma unroll
    for (int a = 0; a < 4; a++)
#pragma unroll
        for (int b = 0; b < 4; b++)
#pragma unroll
            for (int r = 0; r < 4; r++) acc[a][b][r] = 0.f;

    const int aoff[3] = {T_AH, T_AH, T_AL};
    const int boff[3] = {T_BH, T_BL, T_BH};

#pragma unroll
    for (int pass = 0; pass < 3; pass++) {
        uint32_t abase = sbase + aoff[pass];
        uint32_t bbase = sbase + boff[pass];
#pragma unroll
        for (int k0 = 0; k0 < 64; k0 += 16) {
            int cbase = k0 >> 3;
            uint32_t a[4][4];
#pragma unroll
            for (int mi = 0; mi < 4; mi++) {
                int row = wm * 64 + mi * 16 + (lane & 15);
                int ch = cbase + (lane >> 4);
                uint32_t addr = abase + row * 128 + ((ch ^ (row & 7)) << 4);
                ldsm_x4(a[mi][0], a[mi][1], a[mi][2], a[mi][3], addr);
            }
            uint32_t b[4][2];
#pragma unroll
            for (int np = 0; np < 2; np++) {
                int row = wn * 32 + np * 16 + (lane & 7) + ((lane >> 4) << 3);
                int ch = cbase + ((lane >> 3) & 1);
                uint32_t addr = bbase + row * 128 + ((ch ^ (row & 7)) << 4);
                uint32_t r0, r1, r2, r3;
                ldsm_x4(r0, r1, r2, r3, addr);
                b[np * 2 + 0][0] = r0; b[np * 2 + 0][1] = r1;
                b[np * 2 + 1][0] = r2; b[np * 2 + 1][1] = r3;
            }
#pragma unroll
            for (int mi = 0; mi < 4; mi++)
#pragma unroll
                for (int ni = 0; ni < 4; ni++)
                    mma16816(acc[mi][ni][0], acc[mi][ni][1], acc[mi][ni][2], acc[mi][ni][3],
                             a[mi][0], a[mi][1], a[mi][2], a[mi][3],
                             b[ni][0], b[ni][1]);
        }
    }

#pragma unroll
    for (int mi = 0; mi < 4; mi++)
#pragma unroll
        for (int ni = 0; ni < 4; ni++)
#pragma unroll
            for (int r = 0; r < 4; r++) acc[mi][ni][r] *= 100.f;

    float* En = E + (size_t)n * HWA * HWA;
    int rbase = p0 + wm * 64 + (lane >> 2);
    int cbase2 = q0 + wn * 32 + (lane & 3) * 2;
#pragma unroll
    for (int mi = 0; mi < 4; mi++) {
#pragma unroll
        for (int ni = 0; ni < 4; ni++) {
            float2 v0 = make_float2(acc[mi][ni][0], acc[mi][ni][1]);
            float2 v1 = make_float2(acc[mi][ni][2], acc[mi][ni][3]);
            size_t r0 = (size_t)(rbase + mi * 16) * HWA + cbase2 + ni * 8;
            size_t r1 = r0 + 8 * HWA;
            *(float2*)(En + r0) = v0;
            *(float2*)(En + r1) = v1;
        }
    }

    // softmax stats over the 128 p-rows of this tile, per column
    float cm[8], cs[8];
#pragma unroll
    for (int j = 0; j < 8; j++) {
        int ni = j >> 1, half = j & 1;
        float m = acc[0][ni][half];
#pragma unroll
        for (int mi = 0; mi < 4; mi++) {
            m = fmaxf(m, acc[mi][ni][half]);
            m = fmaxf(m, acc[mi][ni][half + 2]);
        }
        float s = 0.f;
#pragma unroll
        for (int mi = 0; mi < 4; mi++) {
            s += __expf(acc[mi][ni][half] - m);
            s += __expf(acc[mi][ni][half + 2] - m);
        }
        cm[j] = m; cs[j] = s;
    }
#pragma unroll
    for (int off = 4; off <= 16; off <<= 1) {
#pragma unroll
        for (int j = 0; j < 8; j++) {
            float om = __shfl_xor_sync(0xFFFFFFFF, cm[j], off);
            float os = __shfl_xor_sync(0xFFFFFFFF, cs[j], off);
            float M = fmaxf(cm[j], om);
            cs[j] = cs[j] * __expf(cm[j] - M) + os * __expf(om - M);
            cm[j] = M;
        }
    }
    if ((lane >> 2) == 0) {
#pragma unroll
        for (int j = 0; j < 8; j++) {
            int cl = (j >> 1) * 8 + (lane & 3) * 2 + (j & 1);
            sstat[wm][wn][cl][0] = cm[j];
            sstat[wm][wn][cl][1] = cs[j];
        }
    }
    __syncthreads();
    if (tid < 128) {
        int wn2 = tid >> 5, cl = tid & 31;
        float m0 = sstat[0][wn2][cl][0], s0 = sstat[0][wn2][cl][1];
        float m1 = sstat[1][wn2][cl][0], s1 = sstat[1][wn2][cl][1];
        float M = fmaxf(m0, m1);
        float S = s0 * __expf(m0 - M) + s1 * __expf(m1 - M);
        size_t idx = ((size_t)(n * 32 + blockIdx.y)) * HWA + q0 + tid;
        tmax[idx] = M;
        tsum[idx] = S;
    }
}

// ---------------- combine per-tile stats -> per-(n,q) M and 1/L ----------------
__global__ void k_stats_final(const float* __restrict__ tmax, const float* __restrict__ tsum,
                              float* __restrict__ Mv, float* __restrict__ Lv) {
    int n = blockIdx.y;
    int q = blockIdx.x * 128 + threadIdx.x;
    float M = -1e30f;
#pragma unroll 4
    for (int pt = 0; pt < 32; pt++)
        M = fmaxf(M, tmax[((size_t)(n * 32 + pt)) * HWA + q]);
    float L = 0.f;
#pragma unroll 4
    for (int pt = 0; pt < 32; pt++) {
        size_t idx = ((size_t)(n * 32 + pt)) * HWA + q;
        L += tsum[idx] * __expf(tmax[idx] - M);
    }
    Mv[n * HWA + q] = M;
    Lv[n * HWA + q] = 1.f / L;
}

// ---------------- single-pass softmax write + fc_warp einsum; 1024 thr ----------------
__global__ void __launch_bounds__(1024)
k_softmax_fused(float* __restrict__ E, const float* __restrict__ Mv,
                const float* __restrict__ Lv, const float* __restrict__ fc,
                float* __restrict__ warp) {
    int ql = threadIdx.x & 31;
    int pg = threadIdx.x >> 5;          // 0..31
    int n = blockIdx.y;
    int q = blockIdx.x * 32 + ql;
    float* En = E + (size_t)n * HWA * HWA;
    float M = Mv[n * HWA + q];
    float Li = Lv[n * HWA + q];

    const float* f0 = fc + (size_t)(n * 3 + 0) * HWA;
    const float* f1 = fc + (size_t)(n * 3 + 1) * HWA;
    const float* f2 = fc + (size_t)(n * 3 + 2) * HWA;
    float w0 = 0.f, w1 = 0.f, w2 = 0.f;
#pragma unroll 4
    for (int p = pg; p < HWA; p += 32) {
        size_t off = (size_t)p * HWA + q;
        float w = __expf(En[off] - M) * Li;
        En[off] = w;
        w0 += __ldg(f0 + p) * w;
        w1 += __ldg(f1 + p) * w;
        w2 += __ldg(f2 + p) * w;
    }
    __shared__ float sw[3][32][33];
    sw[0][pg][ql] = w0; sw[1][pg][ql] = w1; sw[2][pg][ql] = w2;
    __syncthreads();
    if (pg < 3) {
        // warp pg handles channel pg: lane ql reduces 32 partials of column ql
        float a = 0.f;
#pragma unroll
        for (int g = 0; g < 32; g++) a += sw[pg][g][ql];
        warp[(size_t)(n * 3 + pg) * HWA + q] = a;
    }
}

// ---------------- 3x3 conv, reflect pad 1, stride 2, 3->3 channels ----------------
__global__ void k_conv_refl_s2(const float* __restrict__ x, const float* __restrict__ W,
                               const float* __restrict__ b, float* __restrict__ y, int Hin) {
    int Hout = Hin / 2;
    int total = NB * 3 * Hout * Hout;
    int idx = blockIdx.x * 256 + threadIdx.x;
    if (idx >= total) return;
    int ow = idx % Hout; int t = idx / Hout;
    int oh = t % Hout; t /= Hout;
    int co = t % 3; int n = t / 3;
    float s = b[co];
#pragma unroll
    for (int ci = 0; ci < 3; ci++) {
        const float* xp = x + (size_t)((n * 3 + ci) * Hin) * Hin;
#pragma unroll
        for (int kh = 0; kh < 3; kh++) {
            int ih = 2 * oh + kh - 1;
            if (ih < 0) ih = -ih; else if (ih >= Hin) ih = 2 * Hin - 2 - ih;
#pragma unroll
            for (int kw = 0; kw < 3; kw++) {
                int iw = 2 * ow + kw - 1;
                if (iw < 0) iw = -iw; else if (iw >= Hin) iw = 2 * Hin - 2 - iw;
                s += W[((co * 3 + ci) * 3 + kh) * 3 + kw] * __ldg(xp + ih * Hin + iw);
            }
        }
    }
    y[idx] = s;
}

// ---------------- 3x3 conv, zero pad 1, stride 1, 3->3 channels ----------------
__global__ void k_conv_zero_s1(const float* __restrict__ x, const float* __restrict__ W,
                               const float* __restrict__ b, float* __restrict__ y, int H) {
    int total = NB * 3 * H * H;
    int idx = blockIdx.x * 256 + threadIdx.x;
    if (idx >= total) return;
    int ow = idx % H; int t = idx / H;
    int oh = t % H; t /= H;
    int co = t % 3; int n = t / 3;
    float s = b[co];
#pragma unroll
    for (int ci = 0; ci < 3; ci++) {
        const float* xp = x + (size_t)((n * 3 + ci) * H) * H;
#pragma unroll
        for (int kh = 0; kh < 3; kh++) {
            int ih = oh + kh - 1;
            if (ih < 0 || ih >= H) continue;
#pragma unroll
            for (int kw = 0; kw < 3; kw++) {
                int iw = ow + kw - 1;
                if (iw < 0 || iw >= H) continue;
                s += W[((co * 3 + ci) * 3 + kh) * 3 + kw] * __ldg(xp + ih * H + iw);
            }
        }
    }
    y[idx] = s;
}

// ---------------- bilinear 2x upsample, align_corners=True ----------------
__global__ void k_up2x(const float* __restrict__ x, float* __restrict__ y, int S) {
    int O = 2 * S;
    int total = NB * 3 * O * O;
    int idx = blockIdx.x * 256 + threadIdx.x;
    if (idx >= total) return;
    int ow = idx % O; int t = idx / O;
    int oh = t % O;
    int pl = t / O;  // n*3+c
    float ph = (float)(oh * (S - 1)) / (float)(O - 1);
    float pw = (float)(ow * (S - 1)) / (float)(O - 1);
    int i0 = (int)ph; float fh = ph - (float)i0; int i1 = min(i0 + 1, S - 1);
    int j0 = (int)pw; float fw = pw - (float)j0; int j1 = min(j0 + 1, S - 1);
    const float* xp = x + (size_t)pl * S * S;
    float top = xp[i0 * S + j0] * (1.f - fh) + xp[i1 * S + j0] * fh;
    float bot = xp[i0 * S + j1] * (1.f - fh) + xp[i1 * S + j1] * fh;
    y[idx] = top * (1.f - fw) + bot * fw;
}

// ---------------- host side ----------------
static float* symf(const void* s) {
    void* p = nullptr;
    cudaGetSymbolAddress(&p, s);
    return (float*)p;
}
static __nv_bfloat16* symb(const void* s) {
    void* p = nullptr;
    cudaGetSymbolAddress(&p, s);
    return (__nv_bfloat16*)p;
}

extern "C" void kernel_launch(void* const* d_in, const int* in_sizes, int n_in,
                              void* d_out, int out_size) {
    const float* fa_raw = (const float*)d_in[0];
    const float* fb_raw = (const float*)d_in[1];
    const float* fc_raw = (const float*)d_in[2];
    const float* Wa  = (const float*)d_in[3];
    const float* ba  = (const float*)d_in[4];
    const float* Wb  = (const float*)d_in[5];
    const float* bb  = (const float*)d_in[6];
    const float* Wc1 = (const float*)d_in[7];
    const float* bc1 = (const float*)d_in[8];
    const float* Wc2 = (const float*)d_in[9];
    const float* bc2 = (const float*)d_in[10];
    const float* Wu1 = (const float*)d_in[11];
    const float* bu1 = (const float*)d_in[12];
    const float* Wu2 = (const float*)d_in[13];
    const float* bu2 = (const float*)d_in[14];

    float* out = (float*)d_out;
    float* fcw  = out;                               // [2,3,256,256]
    float* corr = out + (size_t)NB * 3 * 256 * 256;  // [2,4096,4096]

    float* fa   = symf(g_fa);
    float* fb   = symf(g_fb);
    float* mA   = symf(g_meanA);
    float* mB   = symf(g_meanB);
    __nv_bfloat16* faH = symb(g_faH);
    __nv_bfloat16* faL = symb(g_faL);
    __nv_bfloat16* fbH = symb(g_fbH);
    __nv_bfloat16* fbL = symb(g_fbL);
    float* fc1  = symf(g_fc1);
    float* fc2  = symf(g_fc2);
    float* warp = symf(g_warp);
    float* up1  = symf(g_up1);
    float* c1   = symf(g_c1);
    float* up2  = symf(g_up2);
    float* tmax = symf(g_tmax);
    float* tsum = symf(g_tsum);
    float* Mv   = symf(g_M);
    float* Lv   = symf(g_Li);

    cudaFuncSetAttribute(k_energy_mma, cudaFuncAttributeMaxDynamicSharedMemorySize, EGY_DSMEM);

    // fa / fb feature path (merged launches)
    k_gemm1x1_ab<<<dim3(64, NB, 2), 256>>>(fa_raw, fb_raw, Wa, Wb, ba, bb, fa, fb);
    k_in_leaky_ab<<<dim3(NB * CQ, 2), 1024>>>(fa, fb, mA, mB);
    k_colnorm_bf16<<<dim3(16, NB, 2), 256>>>(fa, fb, mA, mB, faH, faL, fbH, fbL);

    // fc downsample path
    k_conv_refl_s2<<<(NB * 3 * 128 * 128 + 255) / 256, 256>>>(fc_raw, Wc1, bc1, fc1, 256);
    k_in_leaky<<<NB * 3, 1024>>>(fc1, 128 * 128);
    k_conv_refl_s2<<<(NB * 3 * 64 * 64 + 255) / 256, 256>>>(fc1, Wc2, bc2, fc2, 128);
    k_in_leaky<<<NB * 3, 1024>>>(fc2, 64 * 64);

    // energy GEMM + per-tile softmax stats into corr region of d_out
    k_energy_mma<<<dim3(32, 32, NB), 256, EGY_DSMEM>>>(fbH, fbL, faH, faL, corr, tmax, tsum);
    k_stats_final<<<dim3(32, NB), 128>>>(tmax, tsum, Mv, Lv);

    // single-pass softmax write (in place) + fc_warp einsum
    k_softmax_fused<<<dim3(128, NB), 1024>>>(corr, Mv, Lv, fc2, warp);

    // upsample block 1: 64 -> 128 (separate up + conv: cheaper than fused recompute)
    k_up2x<<<(NB * 3 * 128 * 128 + 255) / 256, 256>>>(warp, up1, 64);
    k_conv_zero_s1<<<(NB * 3 * 128 * 128 + 255) / 256, 256>>>(up1, Wu1, bu1, c1, 128);
    k_in_leaky<<<NB * 3, 1024>>>(c1, 128 * 128);

    // upsample block 2: 128 -> 256, final result into d_out fc_warp region
    k_up2x<<<(NB * 3 * 256 * 256 + 255) / 256, 256>>>(c1, up2, 128);
    k_conv_zero_s1<<<(NB * 3 * 256 * 256 + 255) / 256, 256>>>(up2, Wu2, bu2, fcw, 256);
    k_in_leaky<<<NB * 3, 1024>>>(fcw, 256 * 256);
}

// round 13
// speedup vs baseline: 2.2815x; 1.1461x over previous
#include <cuda_runtime.h>
#include <cuda_bf16.h>
#include <cstdint>
#include <math.h>

// ---------------- static scratch (no allocations allowed) ----------------
#define NB 2
#define CQ 64
#define HWA 4096         // 64*64 spatial positions

__device__ float g_fa[NB*CQ*HWA];        // fp32 features, pre-norm
__device__ float g_fb[NB*CQ*HWA];
__device__ float g_meanA[NB*CQ];
__device__ float g_meanB[NB*CQ];
__device__ __nv_bfloat16 g_faH[NB*HWA*CQ];  // transposed [q][c] bf16 hi/lo
__device__ __nv_bfloat16 g_faL[NB*HWA*CQ];
__device__ __nv_bfloat16 g_fbH[NB*HWA*CQ];
__device__ __nv_bfloat16 g_fbL[NB*HWA*CQ];
__device__ float g_fc1[NB*3*128*128];
__device__ float g_fc2[NB*3*64*64];
__device__ float g_warp[NB*3*4096];
__device__ float g_up1[NB*3*128*128];
__device__ float g_c1[NB*3*128*128];
__device__ float g_up2[NB*3*256*256];
__device__ float g_tmax[NB*32*HWA];      // per (n, p-tile, q) partial softmax stats
__device__ float g_tsum[NB*32*HWA];
__device__ float g_M[NB*HWA];            // final per-(n,q) max
__device__ float g_Li[NB*HWA];           // final per-(n,q) 1/sumexp
__device__ float2 g_part[1536];          // per-block (sum, sumsq) partials for conv->IN

__device__ __forceinline__ uint32_t smem_u32(const void* p) {
    uint32_t a;
    asm("{ .reg .u64 t; cvta.to.shared.u64 t, %1; cvt.u32.u64 %0, t; }" : "=r"(a) : "l"(p));
    return a;
}

// ---------------- 1x1 conv as GEMM, fa and fb in one launch ----------------
// grid (128, NB, 2), block 256 = 32 p-lanes x 8 co-groups of 8
__global__ void k_gemm1x1_ab(const float* __restrict__ xa, const float* __restrict__ xb,
                             const float* __restrict__ Wa, const float* __restrict__ Wb,
                             const float* __restrict__ ba, const float* __restrict__ bb,
                             float* __restrict__ oa, float* __restrict__ ob) {
    const float* x = blockIdx.z ? xb : xa;
    const float* W = blockIdx.z ? Wb : Wa;
    const float* b = blockIdx.z ? bb : ba;
    float* out = blockIdx.z ? ob : oa;

    __shared__ float sWt[64][68];   // [ci_local][co], padded rows
    int pl  = threadIdx.x & 31;
    int cog = threadIdx.x >> 5;
    int p   = blockIdx.x * 32 + pl;
    int n   = blockIdx.y;
    const float* xn = x + (size_t)n * 256 * HWA;

    float acc[8];
#pragma unroll
    for (int k = 0; k < 8; k++) acc[k] = 0.f;

    for (int ci0 = 0; ci0 < 256; ci0 += 64) {
        __syncthreads();
        for (int i = threadIdx.x; i < 64 * 64; i += 256) {
            int cl = i & 63, co = i >> 6;
            sWt[cl][co] = W[co * 256 + ci0 + cl];
        }
        __syncthreads();
#pragma unroll 4
        for (int cl = 0; cl < 64; cl++) {
            float xv = xn[(size_t)(ci0 + cl) * HWA + p];
            const float4* wp = (const float4*)&sWt[cl][cog * 8];
            float4 w0 = wp[0], w1 = wp[1];
            acc[0] += w0.x * xv; acc[1] += w0.y * xv;
            acc[2] += w0.z * xv; acc[3] += w0.w * xv;
            acc[4] += w1.x * xv; acc[5] += w1.y * xv;
            acc[6] += w1.z * xv; acc[7] += w1.w * xv;
        }
    }
    float* on = out + (size_t)n * CQ * HWA;
#pragma unroll
    for (int k = 0; k < 8; k++) {
        int co = cog * 8 + k;
        on[(size_t)co * HWA + p] = acc[k] + b[co];
    }
}

// ---------------- fa/fb instance norm + leaky + post-act mean (one launch) ----------------
__global__ void k_in_leaky_ab(float* __restrict__ fa, float* __restrict__ fb,
                              float* __restrict__ mA, float* __restrict__ mB) {
    float* buf = blockIdx.y ? fb : fa;
    float* mo  = blockIdx.y ? mB : mA;
    float* p = buf + (size_t)blockIdx.x * HWA;
    int t = threadIdx.x;
    int nt = blockDim.x;
    __shared__ float red[1024];
    __shared__ float s_mean, s_rstd;

    float s = 0.f;
    for (int i = t; i < HWA; i += nt) s += p[i];
    red[t] = s; __syncthreads();
    for (int o = nt >> 1; o > 0; o >>= 1) { if (t < o) red[t] += red[t + o]; __syncthreads(); }
    if (t == 0) s_mean = red[0] / (float)HWA;
    __syncthreads();
    float mean = s_mean;

    float s2 = 0.f;
    for (int i = t; i < HWA; i += nt) { float d = p[i] - mean; s2 += d * d; }
    red[t] = s2; __syncthreads();
    for (int o = nt >> 1; o > 0; o >>= 1) { if (t < o) red[t] += red[t + o]; __syncthreads(); }
    if (t == 0) s_rstd = rsqrtf(red[0] / (float)HWA + 1e-5f);
    __syncthreads();
    float r = s_rstd;

    float sact = 0.f;
    for (int i = t; i < HWA; i += nt) {
        float v = (p[i] - mean) * r;
        v = v >= 0.f ? v : 0.2f * v;
        p[i] = v;
        sact += v;
    }
    __syncthreads();
    red[t] = sact; __syncthreads();
    for (int o = nt >> 1; o > 0; o >>= 1) { if (t < o) red[t] += red[t + o]; __syncthreads(); }
    if (t == 0) mo[blockIdx.x] = red[0] / (float)HWA;
}

// ---------------- center + column L2 normalize, emit transposed bf16 hi/lo ----------------
__global__ void k_colnorm_bf16(const float* __restrict__ fa, const float* __restrict__ fb,
                               const float* __restrict__ mA, const float* __restrict__ mB,
                               __nv_bfloat16* __restrict__ aH, __nv_bfloat16* __restrict__ aL,
                               __nv_bfloat16* __restrict__ bH, __nv_bfloat16* __restrict__ bL) {
    const float* buf = blockIdx.z ? fb : fa;
    const float* mean = blockIdx.z ? mB : mA;
    __nv_bfloat16* oH = blockIdx.z ? bH : aH;
    __nv_bfloat16* oL = blockIdx.z ? bL : aL;

    int n = blockIdx.y;
    int q = blockIdx.x * 256 + threadIdx.x;
    __shared__ float sm[64];
    if (threadIdx.x < 64) sm[threadIdx.x] = mean[n * 64 + threadIdx.x];
    __syncthreads();
    const float* bn = buf + (size_t)n * CQ * HWA;
    float v[64];
    float s = 0.f;
#pragma unroll
    for (int c = 0; c < 64; c++) {
        float t2 = bn[(size_t)c * HWA + q] - sm[c];
        v[c] = t2; s += t2 * t2;
    }
    float inv = 1.f / (sqrtf(s) + 1e-5f);
    __align__(16) __nv_bfloat16 hb[64];
    __align__(16) __nv_bfloat16 lb[64];
#pragma unroll
    for (int c = 0; c < 64; c++) {
        float f = v[c] * inv;
        __nv_bfloat16 h = __float2bfloat16(f);
        hb[c] = h;
        lb[c] = __float2bfloat16(f - __bfloat162float(h));
    }
    uint4* dH = (uint4*)(oH + ((size_t)n * HWA + q) * 64);
    uint4* dL = (uint4*)(oL + ((size_t)n * HWA + q) * 64);
#pragma unroll
    for (int i = 0; i < 8; i++) {
        dH[i] = ((const uint4*)hb)[i];
        dL[i] = ((const uint4*)lb)[i];
    }
}

// ---------------- energy GEMM via mma.sync bf16 hi/lo split + softmax stats epilogue ----------
#define EGY_DSMEM (4 * 16384)

__device__ __forceinline__ void ldsm_x4(uint32_t& r0, uint32_t& r1, uint32_t& r2, uint32_t& r3,
                                        uint32_t addr) {
    asm volatile("ldmatrix.sync.aligned.m8n8.x4.shared.b16 {%0,%1,%2,%3}, [%4];"
                 : "=r"(r0), "=r"(r1), "=r"(r2), "=r"(r3) : "r"(addr));
}
__device__ __forceinline__ void mma16816(float& d0, float& d1, float& d2, float& d3,
                                         uint32_t a0, uint32_t a1, uint32_t a2, uint32_t a3,
                                         uint32_t b0, uint32_t b1) {
    asm volatile(
        "mma.sync.aligned.m16n8k16.row.col.f32.bf16.bf16.f32 "
        "{%0,%1,%2,%3}, {%4,%5,%6,%7}, {%8,%9}, {%0,%1,%2,%3};"
        : "+f"(d0), "+f"(d1), "+f"(d2), "+f"(d3)
        : "r"(a0), "r"(a1), "r"(a2), "r"(a3), "r"(b0), "r"(b1));
}

__global__ void __launch_bounds__(256, 2)
k_energy_mma(const __nv_bfloat16* __restrict__ AH, const __nv_bfloat16* __restrict__ AL,
             const __nv_bfloat16* __restrict__ BH, const __nv_bfloat16* __restrict__ BL,
             float* __restrict__ E, float* __restrict__ tmax, float* __restrict__ tsum) {
    extern __shared__ __align__(16) char smem[];
    __shared__ float sstat[2][4][32][2];   // [wm][wn][col][{m,s}]
    const int tid = threadIdx.x;
    const int wid = tid >> 5, lane = tid & 31;
    const int wm = wid & 1, wn = wid >> 1;
    const int n = blockIdx.z;
    const int q0 = blockIdx.x * 128, p0 = blockIdx.y * 128;

    const int T_AH = 0, T_AL = 16384, T_BH = 32768, T_BL = 49152;

    {
        const uint4* src[4] = {
            (const uint4*)(AH + ((size_t)n * HWA + p0) * 64),
            (const uint4*)(AL + ((size_t)n * HWA + p0) * 64),
            (const uint4*)(BH + ((size_t)n * HWA + q0) * 64),
            (const uint4*)(BL + ((size_t)n * HWA + q0) * 64)};
        uint4* dst[4] = {(uint4*)(smem + T_AH), (uint4*)(smem + T_AL),
                         (uint4*)(smem + T_BH), (uint4*)(smem + T_BL)};
#pragma unroll
        for (int t4 = 0; t4 < 4; t4++) {
#pragma unroll
            for (int i = 0; i < 4; i++) {
                int g = tid + i * 256;
                int row = g >> 3, ch = g & 7;
                dst[t4][row * 8 + (ch ^ (row & 7))] = src[t4][g];
            }
        }
    }
    __syncthreads();

    const uint32_t sbase = smem_u32(smem);
    float acc[4][4][4];
#pragma unroll
    for (int a = 0; a < 4; a++)
#pragma unroll
        for (int b = 0; b < 4; b++)
#pragma unroll
            for (int r = 0; r < 4; r++) acc[a][b][r] = 0.f;

    const int aoff[3] = {T_AH, T_AH, T_AL};
    const int boff[3] = {T_BH, T_BL, T_BH};

#pragma unroll
    for (int pass = 0; pass < 3; pass++) {
        uint32_t abase = sbase + aoff[pass];
        uint32_t bbase = sbase + boff[pass];
#pragma unroll
        for (int k0 = 0; k0 < 64; k0 += 16) {
            int cbase = k0 >> 3;
            uint32_t a[4][4];
#pragma unroll
            for (int mi = 0; mi < 4; mi++) {
                int row = wm * 64 + mi * 16 + (lane & 15);
                int ch = cbase + (lane >> 4);
                uint32_t addr = abase + row * 128 + ((ch ^ (row & 7)) << 4);
                ldsm_x4(a[mi][0], a[mi][1], a[mi][2], a[mi][3], addr);
            }
            uint32_t b[4][2];
#pragma unroll
            for (int np = 0; np < 2; np++) {
                int row = wn * 32 + np * 16 + (lane & 7) + ((lane >> 4) << 3);
                int ch = cbase + ((lane >> 3) & 1);
                uint32_t addr = bbase + row * 128 + ((ch ^ (row & 7)) << 4);
                uint32_t r0, r1, r2, r3;
                ldsm_x4(r0, r1, r2, r3, addr);
                b[np * 2 + 0][0] = r0; b[np * 2 + 0][1] = r1;
                b[np * 2 + 1][0] = r2; b[np * 2 + 1][1] = r3;
            }
#pragma unroll
            for (int mi = 0; mi < 4; mi++)
#pragma unroll
                for (int ni = 0; ni < 4; ni++)
                    mma16816(acc[mi][ni][0], acc[mi][ni][1], acc[mi][ni][2], acc[mi][ni][3],
                             a[mi][0], a[mi][1], a[mi][2], a[mi][3],
                             b[ni][0], b[ni][1]);
        }
    }

#pragma unroll
    for (int mi = 0; mi < 4; mi++)
#pragma unroll
        for (int ni = 0; ni < 4; ni++)
#pragma unroll
            for (int r = 0; r < 4; r++) acc[mi][ni][r] *= 100.f;

    float* En = E + (size_t)n * HWA * HWA;
    int rbase = p0 + wm * 64 + (lane >> 2);
    int cbase2 = q0 + wn * 32 + (lane & 3) * 2;
#pragma unroll
    for (int mi = 0; mi < 4; mi++) {
#pragma unroll
        for (int ni = 0; ni < 4; ni++) {
            float2 v0 = make_float2(acc[mi][ni][0], acc[mi][ni][1]);
            float2 v1 = make_float2(acc[mi][ni][2], acc[mi][ni][3]);
            size_t r0 = (size_t)(rbase + mi * 16) * HWA + cbase2 + ni * 8;
            size_t r1 = r0 + 8 * HWA;
            *(float2*)(En + r0) = v0;
            *(float2*)(En + r1) = v1;
        }
    }

    float cm[8], cs[8];
#pragma unroll
    for (int j = 0; j < 8; j++) {
        int ni = j >> 1, half = j & 1;
        float m = acc[0][ni][half];
#pragma unroll
        for (int mi = 0; mi < 4; mi++) {
            m = fmaxf(m, acc[mi][ni][half]);
            m = fmaxf(m, acc[mi][ni][half + 2]);
        }
        float s = 0.f;
#pragma unroll
        for (int mi = 0; mi < 4; mi++) {
            s += __expf(acc[mi][ni][half] - m);
            s += __expf(acc[mi][ni][half + 2] - m);
        }
        cm[j] = m; cs[j] = s;
    }
#pragma unroll
    for (int off = 4; off <= 16; off <<= 1) {
#pragma unroll
        for (int j = 0; j < 8; j++) {
            float om = __shfl_xor_sync(0xFFFFFFFF, cm[j], off);
            float os = __shfl_xor_sync(0xFFFFFFFF, cs[j], off);
            float M = fmaxf(cm[j], om);
            cs[j] = cs[j] * __expf(cm[j] - M) + os * __expf(om - M);
            cm[j] = M;
        }
    }
    if ((lane >> 2) == 0) {
#pragma unroll
        for (int j = 0; j < 8; j++) {
            int cl = (j >> 1) * 8 + (lane & 3) * 2 + (j & 1);
            sstat[wm][wn][cl][0] = cm[j];
            sstat[wm][wn][cl][1] = cs[j];
        }
    }
    __syncthreads();
    if (tid < 128) {
        int wn2 = tid >> 5, cl = tid & 31;
        float m0 = sstat[0][wn2][cl][0], s0 = sstat[0][wn2][cl][1];
        float m1 = sstat[1][wn2][cl][0], s1 = sstat[1][wn2][cl][1];
        float M = fmaxf(m0, m1);
        float S = s0 * __expf(m0 - M) + s1 * __expf(m1 - M);
        size_t idx = ((size_t)(n * 32 + blockIdx.y)) * HWA + q0 + tid;
        tmax[idx] = M;
        tsum[idx] = S;
    }
}

// ---------------- combine per-tile stats -> per-(n,q) M and 1/L ----------------
__global__ void k_stats_final(const float* __restrict__ tmax, const float* __restrict__ tsum,
                              float* __restrict__ Mv, float* __restrict__ Lv) {
    int n = blockIdx.y;
    int q = blockIdx.x * 128 + threadIdx.x;
    float M = -1e30f;
#pragma unroll 4
    for (int pt = 0; pt < 32; pt++)
        M = fmaxf(M, tmax[((size_t)(n * 32 + pt)) * HWA + q]);
    float L = 0.f;
#pragma unroll 4
    for (int pt = 0; pt < 32; pt++) {
        size_t idx = ((size_t)(n * 32 + pt)) * HWA + q;
        L += tsum[idx] * __expf(tmax[idx] - M);
    }
    Mv[n * HWA + q] = M;
    Lv[n * HWA + q] = 1.f / L;
}

// ---------------- single-pass softmax write + fc_warp einsum; 1024 thr ----------------
__global__ void __launch_bounds__(1024)
k_softmax_fused(float* __restrict__ E, const float* __restrict__ Mv,
                const float* __restrict__ Lv, const float* __restrict__ fc,
                float* __restrict__ warp) {
    int ql = threadIdx.x & 31;
    int pg = threadIdx.x >> 5;          // 0..31
    int n = blockIdx.y;
    int q = blockIdx.x * 32 + ql;
    float* En = E + (size_t)n * HWA * HWA;
    float M = Mv[n * HWA + q];
    float Li = Lv[n * HWA + q];

    const float* f0 = fc + (size_t)(n * 3 + 0) * HWA;
    const float* f1 = fc + (size_t)(n * 3 + 1) * HWA;
    const float* f2 = fc + (size_t)(n * 3 + 2) * HWA;
    float w0 = 0.f, w1 = 0.f, w2 = 0.f;
#pragma unroll 4
    for (int p = pg; p < HWA; p += 32) {
        size_t off = (size_t)p * HWA + q;
        float w = __expf(En[off] - M) * Li;
        En[off] = w;
        w0 += __ldg(f0 + p) * w;
        w1 += __ldg(f1 + p) * w;
        w2 += __ldg(f2 + p) * w;
    }
    __shared__ float sw[3][32][33];
    sw[0][pg][ql] = w0; sw[1][pg][ql] = w1; sw[2][pg][ql] = w2;
    __syncthreads();
    if (pg < 3) {
        float a = 0.f;
#pragma unroll
        for (int g = 0; g < 32; g++) a += sw[pg][g][ql];
        warp[(size_t)(n * 3 + pg) * HWA + q] = a;
    }
}

// ---------------- block-level (sum, sumsq) epilogue shared by conv kernels ----------------
__device__ __forceinline__ void block_stats(float s, float2* part) {
    __shared__ float2 red[256];
    int t = threadIdx.x;
    red[t] = make_float2(s, s * s);
    __syncthreads();
    for (int o = 128; o > 0; o >>= 1) {
        if (t < o) { red[t].x += red[t + o].x; red[t].y += red[t + o].y; }
        __syncthreads();
    }
    if (t == 0) part[blockIdx.x] = red[0];
}

// ---------------- 3x3 conv, reflect pad 1, stride 2, 3->3 ch, + partial stats ----------------
__global__ void k_conv_refl_s2(const float* __restrict__ x, const float* __restrict__ W,
                               const float* __restrict__ b, float* __restrict__ y, int Hin,
                               float2* __restrict__ part) {
    int Hout = Hin / 2;
    int idx = blockIdx.x * 256 + threadIdx.x;
    int ow = idx % Hout; int t = idx / Hout;
    int oh = t % Hout; t /= Hout;
    int co = t % 3; int n = t / 3;
    float s = b[co];
#pragma unroll
    for (int ci = 0; ci < 3; ci++) {
        const float* xp = x + (size_t)((n * 3 + ci) * Hin) * Hin;
#pragma unroll
        for (int kh = 0; kh < 3; kh++) {
            int ih = 2 * oh + kh - 1;
            if (ih < 0) ih = -ih; else if (ih >= Hin) ih = 2 * Hin - 2 - ih;
#pragma unroll
            for (int kw = 0; kw < 3; kw++) {
                int iw = 2 * ow + kw - 1;
                if (iw < 0) iw = -iw; else if (iw >= Hin) iw = 2 * Hin - 2 - iw;
                s += W[((co * 3 + ci) * 3 + kh) * 3 + kw] * __ldg(xp + ih * Hin + iw);
            }
        }
    }
    y[idx] = s;
    block_stats(s, part);
}

// ---------------- 3x3 conv, zero pad 1, stride 1, 3->3 ch, + partial stats ----------------
__global__ void k_conv_zero_s1(const float* __restrict__ x, const float* __restrict__ W,
                               const float* __restrict__ b, float* __restrict__ y, int H,
                               float2* __restrict__ part) {
    int idx = blockIdx.x * 256 + threadIdx.x;
    int ow = idx % H; int t = idx / H;
    int oh = t % H; t /= H;
    int co = t % 3; int n = t / 3;
    float s = b[co];
#pragma unroll
    for (int ci = 0; ci < 3; ci++) {
        const float* xp = x + (size_t)((n * 3 + ci) * H) * H;
#pragma unroll
        for (int kh = 0; kh < 3; kh++) {
            int ih = oh + kh - 1;
            if (ih < 0 || ih >= H) continue;
#pragma unroll
            for (int kw = 0; kw < 3; kw++) {
                int iw = ow + kw - 1;
                if (iw < 0 || iw >= H) continue;
                s += W[((co * 3 + ci) * 3 + kh) * 3 + kw] * __ldg(xp + ih * H + iw);
            }
        }
    }
    y[idx] = s;
    block_stats(s, part);
}

// ---------------- IN apply: reduce partials, normalize + leaky, fully parallel ----------------
__global__ void k_in_apply(float* __restrict__ buf, const float2* __restrict__ part, int bpp) {
    __shared__ float s_mean, s_rstd;
    int plane = blockIdx.x / bpp;
    if (threadIdx.x < 32) {
        float s1 = 0.f, s2 = 0.f;
        for (int i = threadIdx.x; i < bpp; i += 32) {
            float2 v = part[plane * bpp + i];
            s1 += v.x; s2 += v.y;
        }
#pragma unroll
        for (int off = 16; off > 0; off >>= 1) {
            s1 += __shfl_down_sync(0xFFFFFFFF, s1, off);
            s2 += __shfl_down_sync(0xFFFFFFFF, s2, off);
        }
        if (threadIdx.x == 0) {
            float N = (float)(bpp * 256);
            float mean = s1 / N;
            float var = s2 / N - mean * mean;
            s_mean = mean;
            s_rstd = rsqrtf(var + 1e-5f);
        }
    }
    __syncthreads();
    int idx = blockIdx.x * 256 + threadIdx.x;
    float v = (buf[idx] - s_mean) * s_rstd;
    buf[idx] = v >= 0.f ? v : 0.2f * v;
}

// ---------------- bilinear 2x upsample, align_corners=True ----------------
__global__ void k_up2x(const float* __restrict__ x, float* __restrict__ y, int S) {
    int O = 2 * S;
    int total = NB * 3 * O * O;
    int idx = blockIdx.x * 256 + threadIdx.x;
    if (idx >= total) return;
    int ow = idx % O; int t = idx / O;
    int oh = t % O;
    int pl = t / O;  // n*3+c
    float ph = (float)(oh * (S - 1)) / (float)(O - 1);
    float pw = (float)(ow * (S - 1)) / (float)(O - 1);
    int i0 = (int)ph; float fh = ph - (float)i0; int i1 = min(i0 + 1, S - 1);
    int j0 = (int)pw; float fw = pw - (float)j0; int j1 = min(j0 + 1, S - 1);
    const float* xp = x + (size_t)pl * S * S;
    float top = xp[i0 * S + j0] * (1.f - fh) + xp[i1 * S + j0] * fh;
    float bot = xp[i0 * S + j1] * (1.f - fh) + xp[i1 * S + j1] * fh;
    y[idx] = top * (1.f - fw) + bot * fw;
}

// ---------------- host side ----------------
static float* symf(const void* s) {
    void* p = nullptr;
    cudaGetSymbolAddress(&p, s);
    return (float*)p;
}
static __nv_bfloat16* symb(const void* s) {
    void* p = nullptr;
    cudaGetSymbolAddress(&p, s);
    return (__nv_bfloat16*)p;
}

extern "C" void kernel_launch(void* const* d_in, const int* in_sizes, int n_in,
                              void* d_out, int out_size) {
    const float* fa_raw = (const float*)d_in[0];
    const float* fb_raw = (const float*)d_in[1];
    const float* fc_raw = (const float*)d_in[2];
    const float* Wa  = (const float*)d_in[3];
    const float* ba  = (const float*)d_in[4];
    const float* Wb  = (const float*)d_in[5];
    const float* bb  = (const float*)d_in[6];
    const float* Wc1 = (const float*)d_in[7];
    const float* bc1 = (const float*)d_in[8];
    const float* Wc2 = (const float*)d_in[9];
    const float* bc2 = (const float*)d_in[10];
    const float* Wu1 = (const float*)d_in[11];
    const float* bu1 = (const float*)d_in[12];
    const float* Wu2 = (const float*)d_in[13];
    const float* bu2 = (const float*)d_in[14];

    float* out = (float*)d_out;
    float* fcw  = out;                               // [2,3,256,256]
    float* corr = out + (size_t)NB * 3 * 256 * 256;  // [2,4096,4096]

    float* fa   = symf(g_fa);
    float* fb   = symf(g_fb);
    float* mA   = symf(g_meanA);
    float* mB   = symf(g_meanB);
    __nv_bfloat16* faH = symb(g_faH);
    __nv_bfloat16* faL = symb(g_faL);
    __nv_bfloat16* fbH = symb(g_fbH);
    __nv_bfloat16* fbL = symb(g_fbL);
    float* fc1  = symf(g_fc1);
    float* fc2  = symf(g_fc2);
    float* warp = symf(g_warp);
    float* up1  = symf(g_up1);
    float* c1   = symf(g_c1);
    float* up2  = symf(g_up2);
    float* tmax = symf(g_tmax);
    float* tsum = symf(g_tsum);
    float* Mv   = symf(g_M);
    float* Lv   = symf(g_Li);
    float2* part = (float2*)symf(g_part);

    cudaFuncSetAttribute(k_energy_mma, cudaFuncAttributeMaxDynamicSharedMemorySize, EGY_DSMEM);

    // fa / fb feature path (merged launches)
    k_gemm1x1_ab<<<dim3(128, NB, 2), 256>>>(fa_raw, fb_raw, Wa, Wb, ba, bb, fa, fb);
    k_in_leaky_ab<<<dim3(NB * CQ, 2), 1024>>>(fa, fb, mA, mB);
    k_colnorm_bf16<<<dim3(16, NB, 2), 256>>>(fa, fb, mA, mB, faH, faL, fbH, fbL);

    // fc downsample path (conv emits partial stats; apply is fully parallel)
    k_conv_refl_s2<<<384, 256>>>(fc_raw, Wc1, bc1, fc1, 256, part);   // 6 planes x 64 blocks
    k_in_apply<<<384, 256>>>(fc1, part, 64);
    k_conv_refl_s2<<<96, 256>>>(fc1, Wc2, bc2, fc2, 128, part);       // 6 planes x 16 blocks
    k_in_apply<<<96, 256>>>(fc2, part, 16);

    // energy GEMM + per-tile softmax stats into corr region of d_out
    k_energy_mma<<<dim3(32, 32, NB), 256, EGY_DSMEM>>>(fbH, fbL, faH, faL, corr, tmax, tsum);
    k_stats_final<<<dim3(32, NB), 128>>>(tmax, tsum, Mv, Lv);

    // single-pass softmax write (in place) + fc_warp einsum
    k_softmax_fused<<<dim3(128, NB), 1024>>>(corr, Mv, Lv, fc2, warp);

    // upsample block 1: 64 -> 128
    k_up2x<<<384, 256>>>(warp, up1, 64);
    k_conv_zero_s1<<<384, 256>>>(up1, Wu1, bu1, c1, 128, part);       // 6 planes x 64 blocks
    k_in_apply<<<384, 256>>>(c1, part, 64);

    // upsample block 2: 128 -> 256, final result into d_out fc_warp region
    k_up2x<<<1536, 256>>>(c1, up2, 128);
    k_conv_zero_s1<<<1536, 256>>>(up2, Wu2, bu2, fcw, 256, part);     // 6 planes x 256 blocks
    k_in_apply<<<1536, 256>>>(fcw, part, 256);
}

// round 17
// speedup vs baseline: 2.3674x; 1.0377x over previous
#include <cuda_runtime.h>
#include <cuda_bf16.h>
#include <cstdint>
#include <math.h>

// ---------------- static scratch (no allocations allowed) ----------------
#define NB 2
#define CQ 64
#define HWA 4096         // 64*64 spatial positions

__device__ float g_fa[NB*CQ*HWA];        // fp32 features, pre-norm
__device__ float g_fb[NB*CQ*HWA];
__device__ float g_meanA[NB*CQ];
__device__ float g_meanB[NB*CQ];
__device__ __nv_bfloat16 g_faH[NB*HWA*CQ];  // transposed [q][c] bf16 hi/lo
__device__ __nv_bfloat16 g_faL[NB*HWA*CQ];
__device__ __nv_bfloat16 g_fbH[NB*HWA*CQ];
__device__ __nv_bfloat16 g_fbL[NB*HWA*CQ];
__device__ float g_fc1[NB*3*128*128];
__device__ float g_fc2[NB*3*64*64];
__device__ float g_warp[NB*3*4096];
__device__ float g_up1[NB*3*128*128];
__device__ float g_c1[NB*3*128*128];
__device__ float g_up2[NB*3*256*256];
__device__ float g_tsum[NB*32*HWA];      // per (n, p-tile, q) partial sum of exp(e-60)
__device__ float2 g_part[1536];          // per-block (sum, sumsq) partials for conv->IN

#define SOFT_M 60.f                      // fixed softmax shift (valid: |e| <= 100)

__device__ __forceinline__ uint32_t smem_u32(const void* p) {
    uint32_t a;
    asm("{ .reg .u64 t; cvta.to.shared.u64 t, %1; cvt.u32.u64 %0, t; }" : "=r"(a) : "l"(p));
    return a;
}

// ---------------- 1x1 conv as GEMM, fa and fb in one launch ----------------
// grid (128, NB, 2), block 256 = 32 p-lanes x 8 co-groups of 8
__global__ void k_gemm1x1_ab(const float* __restrict__ xa, const float* __restrict__ xb,
                             const float* __restrict__ Wa, const float* __restrict__ Wb,
                             const float* __restrict__ ba, const float* __restrict__ bb,
                             float* __restrict__ oa, float* __restrict__ ob) {
    const float* x = blockIdx.z ? xb : xa;
    const float* W = blockIdx.z ? Wb : Wa;
    const float* b = blockIdx.z ? bb : ba;
    float* out = blockIdx.z ? ob : oa;

    __shared__ float sWt[64][68];   // [ci_local][co], padded rows
    int pl  = threadIdx.x & 31;
    int cog = threadIdx.x >> 5;
    int p   = blockIdx.x * 32 + pl;
    int n   = blockIdx.y;
    const float* xn = x + (size_t)n * 256 * HWA;

    float acc[8];
#pragma unroll
    for (int k = 0; k < 8; k++) acc[k] = 0.f;

    for (int ci0 = 0; ci0 < 256; ci0 += 64) {
        __syncthreads();
        for (int i = threadIdx.x; i < 64 * 64; i += 256) {
            int cl = i & 63, co = i >> 6;
            sWt[cl][co] = W[co * 256 + ci0 + cl];
        }
        __syncthreads();
#pragma unroll 4
        for (int cl = 0; cl < 64; cl++) {
            float xv = xn[(size_t)(ci0 + cl) * HWA + p];
            const float4* wp = (const float4*)&sWt[cl][cog * 8];
            float4 w0 = wp[0], w1 = wp[1];
            acc[0] += w0.x * xv; acc[1] += w0.y * xv;
            acc[2] += w0.z * xv; acc[3] += w0.w * xv;
            acc[4] += w1.x * xv; acc[5] += w1.y * xv;
            acc[6] += w1.z * xv; acc[7] += w1.w * xv;
        }
    }
    float* on = out + (size_t)n * CQ * HWA;
#pragma unroll
    for (int k = 0; k < 8; k++) {
        int co = cog * 8 + k;
        on[(size_t)co * HWA + p] = acc[k] + b[co];
    }
}

// ---------------- fa/fb instance norm + leaky + post-act mean (one launch) ----------------
__global__ void k_in_leaky_ab(float* __restrict__ fa, float* __restrict__ fb,
                              float* __restrict__ mA, float* __restrict__ mB) {
    float* buf = blockIdx.y ? fb : fa;
    float* mo  = blockIdx.y ? mB : mA;
    float* p = buf + (size_t)blockIdx.x * HWA;
    int t = threadIdx.x;
    int nt = blockDim.x;
    __shared__ float red[1024];
    __shared__ float s_mean, s_rstd;

    float s = 0.f;
    for (int i = t; i < HWA; i += nt) s += p[i];
    red[t] = s; __syncthreads();
    for (int o = nt >> 1; o > 0; o >>= 1) { if (t < o) red[t] += red[t + o]; __syncthreads(); }
    if (t == 0) s_mean = red[0] / (float)HWA;
    __syncthreads();
    float mean = s_mean;

    float s2 = 0.f;
    for (int i = t; i < HWA; i += nt) { float d = p[i] - mean; s2 += d * d; }
    red[t] = s2; __syncthreads();
    for (int o = nt >> 1; o > 0; o >>= 1) { if (t < o) red[t] += red[t + o]; __syncthreads(); }
    if (t == 0) s_rstd = rsqrtf(red[0] / (float)HWA + 1e-5f);
    __syncthreads();
    float r = s_rstd;

    float sact = 0.f;
    for (int i = t; i < HWA; i += nt) {
        float v = (p[i] - mean) * r;
        v = v >= 0.f ? v : 0.2f * v;
        p[i] = v;
        sact += v;
    }
    __syncthreads();
    red[t] = sact; __syncthreads();
    for (int o = nt >> 1; o > 0; o >>= 1) { if (t < o) red[t] += red[t + o]; __syncthreads(); }
    if (t == 0) mo[blockIdx.x] = red[0] / (float)HWA;
}

// ---------------- center + column L2 normalize, emit transposed bf16 hi/lo ----------------
__global__ void k_colnorm_bf16(const float* __restrict__ fa, const float* __restrict__ fb,
                               const float* __restrict__ mA, const float* __restrict__ mB,
                               __nv_bfloat16* __restrict__ aH, __nv_bfloat16* __restrict__ aL,
                               __nv_bfloat16* __restrict__ bH, __nv_bfloat16* __restrict__ bL) {
    const float* buf = blockIdx.z ? fb : fa;
    const float* mean = blockIdx.z ? mB : mA;
    __nv_bfloat16* oH = blockIdx.z ? bH : aH;
    __nv_bfloat16* oL = blockIdx.z ? bL : aL;

    int n = blockIdx.y;
    int q = blockIdx.x * 256 + threadIdx.x;
    __shared__ float sm[64];
    if (threadIdx.x < 64) sm[threadIdx.x] = mean[n * 64 + threadIdx.x];
    __syncthreads();
    const float* bn = buf + (size_t)n * CQ * HWA;
    float v[64];
    float s = 0.f;
#pragma unroll
    for (int c = 0; c < 64; c++) {
        float t2 = bn[(size_t)c * HWA + q] - sm[c];
        v[c] = t2; s += t2 * t2;
    }
    float inv = 1.f / (sqrtf(s) + 1e-5f);
    __align__(16) __nv_bfloat16 hb[64];
    __align__(16) __nv_bfloat16 lb[64];
#pragma unroll
    for (int c = 0; c < 64; c++) {
        float f = v[c] * inv;
        __nv_bfloat16 h = __float2bfloat16(f);
        hb[c] = h;
        lb[c] = __float2bfloat16(f - __bfloat162float(h));
    }
    uint4* dH = (uint4*)(oH + ((size_t)n * HWA + q) * 64);
    uint4* dL = (uint4*)(oL + ((size_t)n * HWA + q) * 64);
#pragma unroll
    for (int i = 0; i < 8; i++) {
        dH[i] = ((const uint4*)hb)[i];
        dL[i] = ((const uint4*)lb)[i];
    }
}

// ---------------- energy GEMM (mma.sync bf16 hi/lo) -> stores exp(e-60), sums per column ------
#define EGY_DSMEM (4 * 16384)

__device__ __forceinline__ void ldsm_x4(uint32_t& r0, uint32_t& r1, uint32_t& r2, uint32_t& r3,
                                        uint32_t addr) {
    asm volatile("ldmatrix.sync.aligned.m8n8.x4.shared.b16 {%0,%1,%2,%3}, [%4];"
                 : "=r"(r0), "=r"(r1), "=r"(r2), "=r"(r3) : "r"(addr));
}
__device__ __forceinline__ void mma16816(float& d0, float& d1, float& d2, float& d3,
                                         uint32_t a0, uint32_t a1, uint32_t a2, uint32_t a3,
                                         uint32_t b0, uint32_t b1) {
    asm volatile(
        "mma.sync.aligned.m16n8k16.row.col.f32.bf16.bf16.f32 "
        "{%0,%1,%2,%3}, {%4,%5,%6,%7}, {%8,%9}, {%0,%1,%2,%3};"
        : "+f"(d0), "+f"(d1), "+f"(d2), "+f"(d3)
        : "r"(a0), "r"(a1), "r"(a2), "r"(a3), "r"(b0), "r"(b1));
}

__global__ void __launch_bounds__(256, 2)
k_energy_mma(const __nv_bfloat16* __restrict__ AH, const __nv_bfloat16* __restrict__ AL,
             const __nv_bfloat16* __restrict__ BH, const __nv_bfloat16* __restrict__ BL,
             float* __restrict__ E, float* __restrict__ tsum) {
    extern __shared__ __align__(16) char smem[];
    __shared__ float sstat[2][4][32];   // [wm][wn][col] partial sums
    const int tid = threadIdx.x;
    const int wid = tid >> 5, lane = tid & 31;
    const int wm = wid & 1, wn = wid >> 1;
    const int n = blockIdx.z;
    const int q0 = blockIdx.x * 128, p0 = blockIdx.y * 128;

    const int T_AH = 0, T_AL = 16384, T_BH = 32768, T_BL = 49152;

    {
        const uint4* src[4] = {
            (const uint4*)(AH + ((size_t)n * HWA + p0) * 64),
            (const uint4*)(AL + ((size_t)n * HWA + p0) * 64),
            (const uint4*)(BH + ((size_t)n * HWA + q0) * 64),
            (const uint4*)(BL + ((size_t)n * HWA + q0) * 64)};
        uint4* dst[4] = {(uint4*)(smem + T_AH), (uint4*)(smem + T_AL),
                         (uint4*)(smem + T_BH), (uint4*)(smem + T_BL)};
#pragma unroll
        for (int t4 = 0; t4 < 4; t4++) {
#pragma unroll
            for (int i = 0; i < 4; i++) {
                int g = tid + i * 256;
                int row = g >> 3, ch = g & 7;
                dst[t4][row * 8 + (ch ^ (row & 7))] = src[t4][g];
            }
        }
    }
    __syncthreads();

    const uint32_t sbase = smem_u32(smem);
    float acc[4][4][4];
#pragma unroll
    for (int a = 0; a < 4; a++)
#pragma unroll
        for (int b = 0; b < 4; b++)
#pragma unroll
            for (int r = 0; r < 4; r++) acc[a][b][r] = 0.f;

    const int aoff[3] = {T_AH, T_AH, T_AL};
    const int boff[3] = {T_BH, T_BL, T_BH};

#pragma unroll
    for (int pass = 0; pass < 3; pass++) {
        uint32_t abase = sbase + aoff[pass];
        uint32_t bbase = sbase + boff[pass];
#pragma unroll
        for (int k0 = 0; k0 < 64; k0 += 16) {
            int cbase = k0 >> 3;
            uint32_t a[4][4];
#pragma unroll
            for (int mi = 0; mi < 4; mi++) {
                int row = wm * 64 + mi * 16 + (lane & 15);
                int ch = cbase + (lane >> 4);
                uint32_t addr = abase + row * 128 + ((ch ^ (row & 7)) << 4);
                ldsm_x4(a[mi][0], a[mi][1], a[mi][2], a[mi][3], addr);
            }
            uint32_t b[4][2];
#pragma unroll
            for (int np = 0; np < 2; np++) {
                int row = wn * 32 + np * 16 + (lane & 7) + ((lane >> 4) << 3);
                int ch = cbase + ((lane >> 3) & 1);
                uint32_t addr = bbase + row * 128 + ((ch ^ (row & 7)) << 4);
                uint32_t r0, r1, r2, r3;
                ldsm_x4(r0, r1, r2, r3, addr);
                b[np * 2 + 0][0] = r0; b[np * 2 + 0][1] = r1;
                b[np * 2 + 1][0] = r2; b[np * 2 + 1][1] = r3;
            }
#pragma unroll
            for (int mi = 0; mi < 4; mi++)
#pragma unroll
                for (int ni = 0; ni < 4; ni++)
                    mma16816(acc[mi][ni][0], acc[mi][ni][1], acc[mi][ni][2], acc[mi][ni][3],
                             a[mi][0], a[mi][1], a[mi][2], a[mi][3],
                             b[ni][0], b[ni][1]);
        }
    }

    // exp(100*acc - 60) epilogue: store unnormalized weights, accumulate column sums
    float cs[8];
#pragma unroll
    for (int j = 0; j < 8; j++) cs[j] = 0.f;

    float* En = E + (size_t)n * HWA * HWA;
    int rbase = p0 + wm * 64 + (lane >> 2);
    int cbase2 = q0 + wn * 32 + (lane & 3) * 2;
#pragma unroll
    for (int mi = 0; mi < 4; mi++) {
#pragma unroll
        for (int ni = 0; ni < 4; ni++) {
            float e0 = __expf(100.f * acc[mi][ni][0] - SOFT_M);
            float e1 = __expf(100.f * acc[mi][ni][1] - SOFT_M);
            float e2 = __expf(100.f * acc[mi][ni][2] - SOFT_M);
            float e3 = __expf(100.f * acc[mi][ni][3] - SOFT_M);
            size_t r0 = (size_t)(rbase + mi * 16) * HWA + cbase2 + ni * 8;
            size_t r1 = r0 + 8 * HWA;
            *(float2*)(En + r0) = make_float2(e0, e1);
            *(float2*)(En + r1) = make_float2(e2, e3);
            cs[ni * 2 + 0] += e0 + e2;
            cs[ni * 2 + 1] += e1 + e3;
        }
    }
    // reduce across lanes sharing a column (xor 4, 8, 16)
#pragma unroll
    for (int off = 4; off <= 16; off <<= 1)
#pragma unroll
        for (int j = 0; j < 8; j++)
            cs[j] += __shfl_xor_sync(0xFFFFFFFF, cs[j], off);
    if ((lane >> 2) == 0) {
#pragma unroll
        for (int j = 0; j < 8; j++) {
            int cl = (j >> 1) * 8 + (lane & 3) * 2 + (j & 1);
            sstat[wm][wn][cl] = cs[j];
        }
    }
    __syncthreads();
    if (tid < 128) {
        int wn2 = tid >> 5, cl = tid & 31;
        float S = sstat[0][wn2][cl] + sstat[1][wn2][cl];
        size_t idx = ((size_t)(n * 32 + blockIdx.y)) * HWA + q0 + tid;
        tsum[idx] = S;
    }
}

// ---------------- single-pass normalize + fc_warp einsum; Li computed in-block ----------------
__global__ void __launch_bounds__(1024)
k_softmax_fused(float* __restrict__ E, const float* __restrict__ tsum,
                const float* __restrict__ fc, float* __restrict__ warp) {
    int ql = threadIdx.x & 31;
    int pg = threadIdx.x >> 5;          // 0..31
    int n = blockIdx.y;
    int q = blockIdx.x * 32 + ql;
    float* En = E + (size_t)n * HWA * HWA;

    __shared__ float sLi[32];
    if (threadIdx.x < 32) {
        int qq = blockIdx.x * 32 + threadIdx.x;
        float L = 0.f;
#pragma unroll 4
        for (int pt = 0; pt < 32; pt++)
            L += tsum[((size_t)(n * 32 + pt)) * HWA + qq];
        sLi[threadIdx.x] = 1.f / fmaxf(L, 1e-37f);
    }
    __syncthreads();
    float Li = sLi[ql];

    const float* f0 = fc + (size_t)(n * 3 + 0) * HWA;
    const float* f1 = fc + (size_t)(n * 3 + 1) * HWA;
    const float* f2 = fc + (size_t)(n * 3 + 2) * HWA;
    float w0 = 0.f, w1 = 0.f, w2 = 0.f;
#pragma unroll 4
    for (int p = pg; p < HWA; p += 32) {
        size_t off = (size_t)p * HWA + q;
        float w = En[off] * Li;
        En[off] = w;
        w0 += __ldg(f0 + p) * w;
        w1 += __ldg(f1 + p) * w;
        w2 += __ldg(f2 + p) * w;
    }
    __shared__ float sw[3][32][33];
    sw[0][pg][ql] = w0; sw[1][pg][ql] = w1; sw[2][pg][ql] = w2;
    __syncthreads();
    if (pg < 3) {
        float a = 0.f;
#pragma unroll
        for (int g = 0; g < 32; g++) a += sw[pg][g][ql];
        warp[(size_t)(n * 3 + pg) * HWA + q] = a;
    }
}

// ---------------- block-level (sum, sumsq) epilogue shared by conv kernels ----------------
__device__ __forceinline__ void block_stats(float s, float2* part) {
    __shared__ float2 red[256];
    int t = threadIdx.x;
    red[t] = make_float2(s, s * s);
    __syncthreads();
    for (int o = 128; o > 0; o >>= 1) {
        if (t < o) { red[t].x += red[t + o].x; red[t].y += red[t + o].y; }
        __syncthreads();
    }
    if (t == 0) part[blockIdx.x] = red[0];
}

// ---------------- 3x3 conv, reflect pad 1, stride 2, 3->3 ch, + partial stats ----------------
__global__ void k_conv_refl_s2(const float* __restrict__ x, const float* __restrict__ W,
                               const float* __restrict__ b, float* __restrict__ y, int Hin,
                               float2* __restrict__ part) {
    int Hout = Hin / 2;
    int idx = blockIdx.x * 256 + threadIdx.x;
    int ow = idx % Hout; int t = idx / Hout;
    int oh = t % Hout; t /= Hout;
    int co = t % 3; int n = t / 3;
    float s = b[co];
#pragma unroll
    for (int ci = 0; ci < 3; ci++) {
        const float* xp = x + (size_t)((n * 3 + ci) * Hin) * Hin;
#pragma unroll
        for (int kh = 0; kh < 3; kh++) {
            int ih = 2 * oh + kh - 1;
            if (ih < 0) ih = -ih; else if (ih >= Hin) ih = 2 * Hin - 2 - ih;
#pragma unroll
            for (int kw = 0; kw < 3; kw++) {
                int iw = 2 * ow + kw - 1;
                if (iw < 0) iw = -iw; else if (iw >= Hin) iw = 2 * Hin - 2 - iw;
                s += W[((co * 3 + ci) * 3 + kh) * 3 + kw] * __ldg(xp + ih * Hin + iw);
            }
        }
    }
    y[idx] = s;
    block_stats(s, part);
}

// ---------------- 3x3 conv, zero pad 1, stride 1, 3->3 ch, + partial stats ----------------
__global__ void k_conv_zero_s1(const float* __restrict__ x, const float* __restrict__ W,
                               const float* __restrict__ b, float* __restrict__ y, int H,
                               float2* __restrict__ part) {
    int idx = blockIdx.x * 256 + threadIdx.x;
    int ow = idx % H; int t = idx / H;
    int oh = t % H; t /= H;
    int co = t % 3; int n = t / 3;
    float s = b[co];
#pragma unroll
    for (int ci = 0; ci < 3; ci++) {
        const float* xp = x + (size_t)((n * 3 + ci) * H) * H;
#pragma unroll
        for (int kh = 0; kh < 3; kh++) {
            int ih = oh + kh - 1;
            if (ih < 0 || ih >= H) continue;
#pragma unroll
            for (int kw = 0; kw < 3; kw++) {
                int iw = ow + kw - 1;
                if (iw < 0 || iw >= H) continue;
                s += W[((co * 3 + ci) * 3 + kh) * 3 + kw] * __ldg(xp + ih * H + iw);
            }
        }
    }
    y[idx] = s;
    block_stats(s, part);
}

// ---------------- IN apply: reduce partials, normalize + leaky, fully parallel ----------------
__global__ void k_in_apply(float* __restrict__ buf, const float2* __restrict__ part, int bpp) {
    __shared__ float s_mean, s_rstd;
    int plane = blockIdx.x / bpp;
    if (threadIdx.x < 32) {
        float s1 = 0.f, s2 = 0.f;
        for (int i = threadIdx.x; i < bpp; i += 32) {
            float2 v = part[plane * bpp + i];
            s1 += v.x; s2 += v.y;
        }
#pragma unroll
        for (int off = 16; off > 0; off >>= 1) {
            s1 += __shfl_down_sync(0xFFFFFFFF, s1, off);
            s2 += __shfl_down_sync(0xFFFFFFFF, s2, off);
        }
        if (threadIdx.x == 0) {
            float N = (float)(bpp * 256);
            float mean = s1 / N;
            float var = s2 / N - mean * mean;
            s_mean = mean;
            s_rstd = rsqrtf(var + 1e-5f);
        }
    }
    __syncthreads();
    int idx = blockIdx.x * 256 + threadIdx.x;
    float v = (buf[idx] - s_mean) * s_rstd;
    buf[idx] = v >= 0.f ? v : 0.2f * v;
}

// ---------------- bilinear 2x upsample, align_corners=True ----------------
__global__ void k_up2x(const float* __restrict__ x, float* __restrict__ y, int S) {
    int O = 2 * S;
    int total = NB * 3 * O * O;
    int idx = blockIdx.x * 256 + threadIdx.x;
    if (idx >= total) return;
    int ow = idx % O; int t = idx / O;
    int oh = t % O;
    int pl = t / O;  // n*3+c
    float ph = (float)(oh * (S - 1)) / (float)(O - 1);
    float pw = (float)(ow * (S - 1)) / (float)(O - 1);
    int i0 = (int)ph; float fh = ph - (float)i0; int i1 = min(i0 + 1, S - 1);
    int j0 = (int)pw; float fw = pw - (float)j0; int j1 = min(j0 + 1, S - 1);
    const float* xp = x + (size_t)pl * S * S;
    float top = xp[i0 * S + j0] * (1.f - fh) + xp[i1 * S + j0] * fh;
    float bot = xp[i0 * S + j1] * (1.f - fh) + xp[i1 * S + j1] * fh;
    y[idx] = top * (1.f - fw) + bot * fw;
}

// ---------------- host side ----------------
static float* symf(const void* s) {
    void* p = nullptr;
    cudaGetSymbolAddress(&p, s);
    return (float*)p;
}
static __nv_bfloat16* symb(const void* s) {
    void* p = nullptr;
    cudaGetSymbolAddress(&p, s);
    return (__nv_bfloat16*)p;
}

extern "C" void kernel_launch(void* const* d_in, const int* in_sizes, int n_in,
                              void* d_out, int out_size) {
    const float* fa_raw = (const float*)d_in[0];
    const float* fb_raw = (const float*)d_in[1];
    const float* fc_raw = (const float*)d_in[2];
    const float* Wa  = (const float*)d_in[3];
    const float* ba  = (const float*)d_in[4];
    const float* Wb  = (const float*)d_in[5];
    const float* bb  = (const float*)d_in[6];
    const float* Wc1 = (const float*)d_in[7];
    const float* bc1 = (const float*)d_in[8];
    const float* Wc2 = (const float*)d_in[9];
    const float* bc2 = (const float*)d_in[10];
    const float* Wu1 = (const float*)d_in[11];
    const float* bu1 = (const float*)d_in[12];
    const float* Wu2 = (const float*)d_in[13];
    const float* bu2 = (const float*)d_in[14];

    float* out = (float*)d_out;
    float* fcw  = out;                               // [2,3,256,256]
    float* corr = out + (size_t)NB * 3 * 256 * 256;  // [2,4096,4096]

    float* fa   = symf(g_fa);
    float* fb   = symf(g_fb);
    float* mA   = symf(g_meanA);
    float* mB   = symf(g_meanB);
    __nv_bfloat16* faH = symb(g_faH);
    __nv_bfloat16* faL = symb(g_faL);
    __nv_bfloat16* fbH = symb(g_fbH);
    __nv_bfloat16* fbL = symb(g_fbL);
    float* fc1  = symf(g_fc1);
    float* fc2  = symf(g_fc2);
    float* warp = symf(g_warp);
    float* up1  = symf(g_up1);
    float* c1   = symf(g_c1);
    float* up2  = symf(g_up2);
    float* tsum = symf(g_tsum);
    float2* part = (float2*)symf(g_part);

    cudaFuncSetAttribute(k_energy_mma, cudaFuncAttributeMaxDynamicSharedMemorySize, EGY_DSMEM);

    // fa / fb feature path (merged launches)
    k_gemm1x1_ab<<<dim3(128, NB, 2), 256>>>(fa_raw, fb_raw, Wa, Wb, ba, bb, fa, fb);
    k_in_leaky_ab<<<dim3(NB * CQ, 2), 1024>>>(fa, fb, mA, mB);
    k_colnorm_bf16<<<dim3(16, NB, 2), 256>>>(fa, fb, mA, mB, faH, faL, fbH, fbL);

    // fc downsample path (conv emits partial stats; apply is fully parallel)
    k_conv_refl_s2<<<384, 256>>>(fc_raw, Wc1, bc1, fc1, 256, part);   // 6 planes x 64 blocks
    k_in_apply<<<384, 256>>>(fc1, part, 64);
    k_conv_refl_s2<<<96, 256>>>(fc1, Wc2, bc2, fc2, 128, part);       // 6 planes x 16 blocks
    k_in_apply<<<96, 256>>>(fc2, part, 16);

    // energy GEMM: stores exp(e-60) into corr region + per-tile column sums
    k_energy_mma<<<dim3(32, 32, NB), 256, EGY_DSMEM>>>(fbH, fbL, faH, faL, corr, tsum);

    // single-pass normalize (in place) + fc_warp einsum (Li reduced in-block)
    k_softmax_fused<<<dim3(128, NB), 1024>>>(corr, tsum, fc2, warp);

    // upsample block 1: 64 -> 128
    k_up2x<<<384, 256>>>(warp, up1, 64);
    k_conv_zero_s1<<<384, 256>>>(up1, Wu1, bu1, c1, 128, part);       // 6 planes x 64 blocks
    k_in_apply<<<384, 256>>>(c1, part, 64);

    // upsample block 2: 128 -> 256, final result into d_out fc_warp region
    k_up2x<<<1536, 256>>>(c1, up2, 128);
    k_conv_zero_s1<<<1536, 256>>>(up2, Wu2, bu2, fcw, 256, part);     // 6 planes x 256 blocks
    k_in_apply<<<1536, 256>>>(fcw, part, 256);
}